// round 3
// baseline (speedup 1.0000x reference)
#include <cuda_runtime.h>
#include <math.h>

#define HID   300
#define G3    900
#define NSEQ  64
#define BATCH 64
#define EMB   1024
#define KCAT  2524
#define HSZ   (BATCH*NSEQ*HID)

// ---------------- device scratch (no cudaMalloc allowed) ----------------
__device__ float g_H[5 * HSZ];                 // H0..H4
__device__ float g_XI[BATCH * NSEQ * G3];      // Q@wih_c.T + bih_c (current layer)
__device__ float g_XP[BATCH * NSEQ * G3];      // Q@whh_p.T + bhh_p
__device__ float g_Wr2[HID * 600];             // [wr0 | wr1] rows
__device__ float g_u[BATCH * 600];             // [u0;u1]
__device__ float g_M[BATCH * HID];             // message M
__device__ float g_G[BATCH * 1800];            // [gh_c(+bhh_c) ; gi_p(+bih_p)]
__device__ float g_kdot[BATCH * NSEQ];
__device__ int   g_start[BATCH * NSEQ];
__device__ float g_Hcat[BATCH * NSEQ * KCAT];
__device__ float g_h1[BATCH * NSEQ * HID];
__device__ float g_h2[BATCH * NSEQ * HID];

__device__ __forceinline__ float sigf(float x) { return 1.0f / (1.0f + expf(-x)); }

__device__ __forceinline__ float blockReduceSum(float v, float* s) {
    int tid = threadIdx.x;
    s[tid] = v; __syncthreads();
    for (int o = 128; o > 0; o >>= 1) { if (tid < o) s[tid] += s[tid + o]; __syncthreads(); }
    float r = s[0]; __syncthreads(); return r;
}
__device__ __forceinline__ float blockReduceMax(float v, float* s) {
    int tid = threadIdx.x;
    s[tid] = v; __syncthreads();
    for (int o = 128; o > 0; o >>= 1) { if (tid < o) s[tid] = fmaxf(s[tid], s[tid + o]); __syncthreads(); }
    float r = s[0]; __syncthreads(); return r;
}

// ---------------- start index per (b,i) ----------------
__global__ void k_start(const int* __restrict__ spk, int* __restrict__ start) {
    int b = blockIdx.x, i = threadIdx.x;
    int s = spk[b * NSEQ + i];
    int last = -1;
    for (int j = 0; j < i; j++)
        if (spk[b * NSEQ + j] == s) last = j;
    start[b * NSEQ + i] = last > 0 ? last : 0;
}

// ---------------- generic C = A@B^T + bias (opt relu) ----------------
// A[M,K] rm, B[N,K] rm, C[M,N] rm.  64x64 tile, BK=16, 4x4 micro, 256 thr.
__global__ void __launch_bounds__(256) gemm_nt(
    const float* __restrict__ A, const float* __restrict__ B,
    const float* __restrict__ bias, float* __restrict__ C,
    int M, int N, int K, int relu)
{
    __shared__ float sA[16][65];
    __shared__ float sB[16][65];
    int tid = threadIdx.x;
    int m0 = blockIdx.y * 64, n0 = blockIdx.x * 64;
    int tm = tid >> 4, tn = tid & 15;
    int lr = tid >> 2, lk = (tid & 3) * 4;
    float acc[4][4];
#pragma unroll
    for (int i = 0; i < 4; i++)
#pragma unroll
        for (int j = 0; j < 4; j++) acc[i][j] = 0.f;

    for (int k0 = 0; k0 < K; k0 += 16) {
#pragma unroll
        for (int q = 0; q < 4; q++) {
            int k = k0 + lk + q;
            sA[lk + q][lr] = (k < K && (m0 + lr) < M) ? A[(m0 + lr) * K + k] : 0.f;
            sB[lk + q][lr] = (k < K && (n0 + lr) < N) ? B[(n0 + lr) * K + k] : 0.f;
        }
        __syncthreads();
#pragma unroll
        for (int kk = 0; kk < 16; kk++) {
            float a[4], bv[4];
#pragma unroll
            for (int i = 0; i < 4; i++) { a[i] = sA[kk][tm * 4 + i]; bv[i] = sB[kk][tn * 4 + i]; }
#pragma unroll
            for (int i = 0; i < 4; i++)
#pragma unroll
                for (int j = 0; j < 4; j++) acc[i][j] += a[i] * bv[j];
        }
        __syncthreads();
    }
#pragma unroll
    for (int i = 0; i < 4; i++) {
        int m = m0 + tm * 4 + i;
        if (m >= M) continue;
#pragma unroll
        for (int j = 0; j < 4; j++) {
            int n = n0 + tn * 4 + j;
            if (n >= N) continue;
            float v = acc[i][j] + (bias ? bias[n] : 0.f);
            if (relu) v = fmaxf(v, 0.f);
            C[m * N + n] = v;
        }
    }
}

// ---------------- skinny GEMM: C[64,N] = A[64,K] @ W^T + bias ----------------
// W rows: row n<nsplit -> W0[n], else W1[n-nsplit]. 32-out x BT-batch tile.
template <int BT>
__global__ void __launch_bounds__(256) skinny_nt(
    const float* __restrict__ A, int K,
    const float* __restrict__ W0, const float* __restrict__ W1, int nsplit,
    const float* __restrict__ b0, const float* __restrict__ b1,
    float* __restrict__ C, int N)
{
    const int RB = BT / 8;
    __shared__ float sW[32][36];
    __shared__ float sA[BT][36];
    int tid = threadIdx.x, nl = tid & 31, wg = tid >> 5;
    int n0 = blockIdx.x * 32, bb = blockIdx.y * BT;
    int wr = tid >> 3, wkq = (tid & 7) * 4;
    float acc[RB];
#pragma unroll
    for (int r = 0; r < RB; r++) acc[r] = 0.f;

    for (int k0 = 0; k0 < K; k0 += 32) {
        int g = n0 + wr;
        const float* Wp = W0; int gr = g;
        if (g >= nsplit) { Wp = W1; gr = g - nsplit; }
#pragma unroll
        for (int q = 0; q < 4; q++) {
            int k = k0 + wkq + q;
            sW[wr][wkq + q] = (g < N && k < K) ? Wp[gr * K + k] : 0.f;
        }
#pragma unroll
        for (int r = 0; r < RB; r++) {
            int k = k0 + nl;
            sA[wg + r * 8][nl] = (k < K) ? A[(bb + wg + r * 8) * K + k] : 0.f;
        }
        __syncthreads();
#pragma unroll
        for (int k4 = 0; k4 < 8; k4++) {
            float4 wv = *reinterpret_cast<float4*>(&sW[nl][k4 * 4]);
#pragma unroll
            for (int r = 0; r < RB; r++) {
                float4 av = *reinterpret_cast<float4*>(&sA[wg + r * 8][k4 * 4]);
                acc[r] += av.x * wv.x + av.y * wv.y + av.z * wv.z + av.w * wv.w;
            }
        }
        __syncthreads();
    }
    int n = n0 + nl;
    if (n < N) {
        float bias = 0.f;
        if (n < nsplit) { if (b0) bias = b0[n]; }
        else            { if (b1) bias = b1[n - nsplit]; }
#pragma unroll
        for (int r = 0; r < RB; r++) C[(bb + wg + r * 8) * N + n] = acc[r] + bias;
    }
}

// ---------------- per-layer init: H1[:,0] = C0+P0, kdot[:,0] ----------------
__global__ void __launch_bounds__(256) k_init(
    const float* __restrict__ Hin, float* __restrict__ H1,
    const float* __restrict__ XI, const float* __restrict__ XP,
    const float* __restrict__ bhh_c, const float* __restrict__ bih_p,
    const float* __restrict__ wk, float* __restrict__ kdot)
{
    __shared__ float s_red[256];
    int b = blockIdx.x, tid = threadIdx.x;
    const float* xi = XI + b * NSEQ * G3;   // row 0
    const float* xp = XP + b * NSEQ * G3;
    const float* x0 = Hin + b * NSEQ * HID;
    float* h1 = H1 + b * NSEQ * HID;
    float kp = 0.f;
    for (int d = tid; d < HID; d += 256) {
        // C0 = gru(x=x0, h=0): gi = xi (has bih_c), gh = bhh_c
        float r  = sigf(xi[d] + bhh_c[d]);
        float z  = sigf(xi[300 + d] + bhh_c[300 + d]);
        float nn = tanhf(xi[600 + d] + r * bhh_c[600 + d]);
        float C0 = (1.f - z) * nn;
        // P0 = gru(x=0, h=x0): gi = bih_p, gh = xp (has bhh_p)
        float r2 = sigf(bih_p[d] + xp[d]);
        float z2 = sigf(bih_p[300 + d] + xp[300 + d]);
        float n2 = tanhf(bih_p[600 + d] + r2 * xp[600 + d]);
        float P0 = (1.f - z2) * n2 + z2 * x0[d];
        float h = C0 + P0;
        h1[d] = h;
        kp += h * wk[d];
    }
    float ks = blockReduceSum(kp, s_red);
    if (tid == 0) kdot[b * NSEQ] = ks;
}

// ---------------- per-step: apply prev update, then attention -> u ----------------
// i in [1..63]: (if i>=2 update row i-1 from g_M/g_G) then softmax/u for step i.
// i == 64: finalize (update row 63 only).
__global__ void __launch_bounds__(256) s1_kernel(
    const float* __restrict__ Hin, float* __restrict__ H1,
    const float* __restrict__ XI, const float* __restrict__ XP,
    const float* __restrict__ wq, const float* __restrict__ wk,
    const float* __restrict__ gatb, int layer,
    const int* __restrict__ spk, const int* __restrict__ start,
    float* __restrict__ kdot,
    const float* __restrict__ Mbuf, const float* __restrict__ Gbuf,
    float* __restrict__ ubuf, int i)
{
    __shared__ float s_red[256];
    __shared__ float s_w[64];
    __shared__ float s_sm[64];
    int b = blockIdx.x, tid = threadIdx.x;

    if (i >= 2) {
        int row = i - 1;
        const float* G  = Gbuf + b * 1800;
        const float* Mv = Mbuf + b * HID;
        const float* xi = XI + (b * NSEQ + row) * G3;
        const float* xp = XP + (b * NSEQ + row) * G3;
        const float* q  = Hin + (b * NSEQ + row) * HID;
        float* h1r = H1 + (b * NSEQ + row) * HID;
        float kp = 0.f;
        for (int d = tid; d < HID; d += 256) {
            float Md = Mv[d];
            // C = gru(x=Q, h=M): gi = xi, gh = G[0:900]
            float r  = sigf(xi[d] + G[d]);
            float z  = sigf(xi[300 + d] + G[300 + d]);
            float nn = tanhf(xi[600 + d] + r * G[600 + d]);
            float Cc = (1.f - z) * nn + z * Md;
            // P = gru(x=M, h=Q): gi = G[900:1800], gh = xp
            float r2 = sigf(G[900 + d] + xp[d]);
            float z2 = sigf(G[1200 + d] + xp[300 + d]);
            float n2 = tanhf(G[1500 + d] + r2 * xp[600 + d]);
            float Pp = (1.f - z2) * n2 + z2 * q[d];
            float h = Cc + Pp;
            h1r[d] = h;
            kp += h * wk[d];
        }
        float ks = blockReduceSum(kp, s_red);
        if (tid == 0) kdot[b * NSEQ + row] = ks;
        __syncthreads();
    }
    if (i > 63) return;

    // qdot
    const float* qrow = Hin + (b * NSEQ + i) * HID;
    float qp = 0.f;
    for (int d = tid; d < HID; d += 256) qp += qrow[d] * wq[d];
    float qd = blockReduceSum(qp, s_red);

    int st = start[b * NSEQ + i];
    int cnt = i - st;
    int spki = spk[b * NSEQ + i];
    float gb = gatb[layer];

    float aj = -1e30f;
    if (tid < cnt) aj = qd + kdot[b * NSEQ + st + tid] + gb;
    float mx = blockReduceMax(aj, s_red);
    float e = (tid < cnt) ? expf(aj - mx) : 0.f;
    float se = blockReduceSum(e, s_red);
    if (tid < cnt) {
        s_w[tid]  = e / se;
        s_sm[tid] = (spk[b * NSEQ + st + tid] == spki) ? 1.f : 0.f;
    }
    __syncthreads();

    // u0[e] = sum_j w*sm*H1[j,e]; u1[e] = sum_j w*(1-sm)*H1[j,e]
    for (int d = tid; d < 600; d += 256) {
        int ei = (d < 300) ? d : d - 300;
        float u0f = (d < 300) ? 1.f : 0.f;
        const float* base = H1 + (b * NSEQ + st) * HID + ei;
        float acc = 0.f;
        for (int j = 0; j < cnt; j++) {
            float m = s_sm[j];
            float sel = u0f * m + (1.f - u0f) * (1.f - m);
            acc += s_w[j] * sel * base[j * HID];
        }
        ubuf[b * 600 + d] = acc;
    }
}

// ---------------- Wr2 = [wr0 | wr1] ----------------
__global__ void k_wr2(const float* __restrict__ wr0, const float* __restrict__ wr1) {
    int idx = blockIdx.x * blockDim.x + threadIdx.x;
    if (idx < 300 * 600) {
        int d = idx / 600, e = idx - d * 600;
        g_Wr2[idx] = (e < 300) ? wr0[d * 300 + e] : wr1[d * 300 + (e - 300)];
    }
}

// ---------------- Hcat = [H0..H4, features] ----------------
__global__ void k_concat(const float* __restrict__ feat) {
    int r = blockIdx.x;  // 0..4095
    for (int c = threadIdx.x; c < KCAT; c += blockDim.x) {
        float v;
        if (c < 1500) {
            int seg = c / 300, off = c - seg * 300;
            v = g_H[seg * HSZ + r * HID + off];
        } else {
            v = feat[r * EMB + (c - 1500)];
        }
        g_Hcat[r * KCAT + c] = v;
    }
}

extern "C" void kernel_launch(void* const* d_in, const int* in_sizes, int n_in,
                              void* d_out, int out_size) {
    const float* features = (const float*)d_in[0];
    const int*   speakers = (const int*)d_in[1];
    const float* w_in   = (const float*)d_in[2];
    const float* b_in   = (const float*)d_in[3];
    const float* gat_wq = (const float*)d_in[4];
    const float* gat_wk = (const float*)d_in[5];
    const float* gat_b  = (const float*)d_in[6];
    const float* wr0    = (const float*)d_in[7];
    const float* wr1    = (const float*)d_in[8];
    const float* wih_c  = (const float*)d_in[9];
    const float* whh_c  = (const float*)d_in[10];
    const float* bih_c  = (const float*)d_in[11];
    const float* bhh_c  = (const float*)d_in[12];
    const float* wih_p  = (const float*)d_in[13];
    const float* whh_p  = (const float*)d_in[14];
    const float* bih_p  = (const float*)d_in[15];
    const float* bhh_p  = (const float*)d_in[16];
    const float* w1 = (const float*)d_in[17];
    const float* b1 = (const float*)d_in[18];
    const float* w2 = (const float*)d_in[19];
    const float* b2 = (const float*)d_in[20];
    const float* w3 = (const float*)d_in[21];
    const float* b3 = (const float*)d_in[22];

    float *H, *XIp, *XPp, *Wr2p, *up, *Mp, *Gp, *kdotp, *Hcatp, *h1p, *h2p;
    int *startp;
    cudaGetSymbolAddress((void**)&H,     g_H);
    cudaGetSymbolAddress((void**)&XIp,   g_XI);
    cudaGetSymbolAddress((void**)&XPp,   g_XP);
    cudaGetSymbolAddress((void**)&Wr2p,  g_Wr2);
    cudaGetSymbolAddress((void**)&up,    g_u);
    cudaGetSymbolAddress((void**)&Mp,    g_M);
    cudaGetSymbolAddress((void**)&Gp,    g_G);
    cudaGetSymbolAddress((void**)&kdotp, g_kdot);
    cudaGetSymbolAddress((void**)&startp,g_start);
    cudaGetSymbolAddress((void**)&Hcatp, g_Hcat);
    cudaGetSymbolAddress((void**)&h1p,   g_h1);
    cudaGetSymbolAddress((void**)&h2p,   g_h2);

    const int MROWS = BATCH * NSEQ;   // 4096

    k_start<<<BATCH, NSEQ>>>(speakers, startp);

    // H0 = relu(features @ w_in.T + b_in)
    gemm_nt<<<dim3((HID + 63) / 64, MROWS / 64), 256>>>(
        features, w_in, b_in, H, MROWS, HID, EMB, 1);

    for (int l = 0; l < 4; l++) {
        const float* Hin = H + l * HSZ;
        float* H1 = H + (l + 1) * HSZ;
        const float* wih_c_l = wih_c + l * G3 * HID;
        const float* whh_c_l = whh_c + l * G3 * HID;
        const float* wih_p_l = wih_p + l * G3 * HID;
        const float* whh_p_l = whh_p + l * G3 * HID;
        const float* bih_c_l = bih_c + l * G3;
        const float* bhh_c_l = bhh_c + l * G3;
        const float* bih_p_l = bih_p + l * G3;
        const float* bhh_p_l = bhh_p + l * G3;
        const float* wq_l = gat_wq + l * HID;
        const float* wk_l = gat_wk + l * HID;

        // XI = Hin @ wih_c.T + bih_c ;  XP = Hin @ whh_p.T + bhh_p
        gemm_nt<<<dim3((G3 + 63) / 64, MROWS / 64), 256>>>(
            Hin, wih_c_l, bih_c_l, XIp, MROWS, G3, HID, 0);
        gemm_nt<<<dim3((G3 + 63) / 64, MROWS / 64), 256>>>(
            Hin, whh_p_l, bhh_p_l, XPp, MROWS, G3, HID, 0);
        k_wr2<<<(300 * 600 + 255) / 256, 256>>>(wr0 + l * HID * HID, wr1 + l * HID * HID);

        k_init<<<BATCH, 256>>>(Hin, H1, XIp, XPp, bhh_c_l, bih_p_l, wk_l, kdotp);

        for (int i = 1; i <= 63; i++) {
            s1_kernel<<<BATCH, 256>>>(Hin, H1, XIp, XPp, wq_l, wk_l, gat_b, l,
                                      speakers, startp, kdotp, Mp, Gp, up, i);
            // M = u @ Wr2^T  (64 x 300, K=600)
            skinny_nt<8><<<dim3(10, 8), 256>>>(
                up, 600, Wr2p, (const float*)nullptr, 300,
                (const float*)nullptr, (const float*)nullptr, Mp, 300);
            // G = M @ [whh_c ; wih_p]^T + [bhh_c ; bih_p]  (64 x 1800, K=300)
            skinny_nt<32><<<dim3(57, 2), 256>>>(
                Mp, 300, whh_c_l, wih_p_l, 900, bhh_c_l, bih_p_l, Gp, 1800);
        }
        // finalize: apply update for row 63
        s1_kernel<<<BATCH, 256>>>(Hin, H1, XIp, XPp, wq_l, wk_l, gat_b, l,
                                  speakers, startp, kdotp, Mp, Gp, up, 64);
    }

    k_concat<<<MROWS, 256>>>(features);

    gemm_nt<<<dim3((HID + 63) / 64, MROWS / 64), 256>>>(
        Hcatp, w1, b1, h1p, MROWS, HID, KCAT, 1);
    gemm_nt<<<dim3((HID + 63) / 64, MROWS / 64), 256>>>(
        h1p, w2, b2, h2p, MROWS, HID, HID, 1);
    gemm_nt<<<dim3(1, MROWS / 64), 256>>>(
        h2p, w3, b3, (float*)d_out, MROWS, 7, HID, 0);
}

// round 4
// speedup vs baseline: 1.0239x; 1.0239x over previous
#include <cuda_runtime.h>
#include <math.h>

#define HID   300
#define G3    900
#define NSEQ  64
#define BATCH 64
#define EMB   1024
#define KCAT  2524
#define HSZ   (BATCH*NSEQ*HID)

// ---------------- device scratch (no cudaMalloc allowed) ----------------
__device__ float g_H[5 * HSZ];                 // H0..H4
__device__ float g_XI[BATCH * NSEQ * G3];      // Q@wih_c.T + bih_c (current layer)
__device__ float g_XP[BATCH * NSEQ * G3];      // Q@whh_p.T + bhh_p
__device__ float g_Wr2[HID * 600];             // [wr0 | wr1] rows
__device__ float g_u[BATCH * 600];             // [u0;u1]
__device__ float g_M[BATCH * HID];             // message M
__device__ float g_G[BATCH * 1800];            // [gh_c(+bhh_c) ; gi_p(+bih_p)]
__device__ float g_kdot[BATCH * NSEQ];
__device__ int   g_start[BATCH * NSEQ];
__device__ float g_Hcat[BATCH * NSEQ * KCAT];
__device__ float g_h1[BATCH * NSEQ * HID];
__device__ float g_h2[BATCH * NSEQ * HID];

__device__ __forceinline__ float sigf(float x) { return 1.0f / (1.0f + expf(-x)); }

__device__ __forceinline__ float blockReduceSum(float v, float* s) {
    int tid = threadIdx.x;
    s[tid] = v; __syncthreads();
    for (int o = 128; o > 0; o >>= 1) { if (tid < o) s[tid] += s[tid + o]; __syncthreads(); }
    float r = s[0]; __syncthreads(); return r;
}
__device__ __forceinline__ float blockReduceMax(float v, float* s) {
    int tid = threadIdx.x;
    s[tid] = v; __syncthreads();
    for (int o = 128; o > 0; o >>= 1) { if (tid < o) s[tid] = fmaxf(s[tid], s[tid + o]); __syncthreads(); }
    float r = s[0]; __syncthreads(); return r;
}

// ---------------- start index per (b,i) ----------------
__global__ void k_start(const int* __restrict__ spk, int* __restrict__ start) {
    int b = blockIdx.x, i = threadIdx.x;
    int s = spk[b * NSEQ + i];
    int last = -1;
    for (int j = 0; j < i; j++)
        if (spk[b * NSEQ + j] == s) last = j;
    start[b * NSEQ + i] = last > 0 ? last : 0;
}

// ---------------- generic C = A@B^T + bias (opt relu) ----------------
// A[M,K] rm, B[N,K] rm, C[M,N] rm.  64x64 tile, BK=16, 4x4 micro, 256 thr.
__global__ void __launch_bounds__(256) gemm_nt(
    const float* __restrict__ A, const float* __restrict__ B,
    const float* __restrict__ bias, float* __restrict__ C,
    int M, int N, int K, int relu)
{
    __shared__ float sA[16][65];
    __shared__ float sB[16][65];
    int tid = threadIdx.x;
    int m0 = blockIdx.y * 64, n0 = blockIdx.x * 64;
    int tm = tid >> 4, tn = tid & 15;
    int lr = tid >> 2, lk = (tid & 3) * 4;
    float acc[4][4];
#pragma unroll
    for (int i = 0; i < 4; i++)
#pragma unroll
        for (int j = 0; j < 4; j++) acc[i][j] = 0.f;

    for (int k0 = 0; k0 < K; k0 += 16) {
#pragma unroll
        for (int q = 0; q < 4; q++) {
            int k = k0 + lk + q;
            sA[lk + q][lr] = (k < K && (m0 + lr) < M) ? A[(m0 + lr) * K + k] : 0.f;
            sB[lk + q][lr] = (k < K && (n0 + lr) < N) ? B[(n0 + lr) * K + k] : 0.f;
        }
        __syncthreads();
#pragma unroll
        for (int kk = 0; kk < 16; kk++) {
            float a[4], bv[4];
#pragma unroll
            for (int i = 0; i < 4; i++) { a[i] = sA[kk][tm * 4 + i]; bv[i] = sB[kk][tn * 4 + i]; }
#pragma unroll
            for (int i = 0; i < 4; i++)
#pragma unroll
                for (int j = 0; j < 4; j++) acc[i][j] += a[i] * bv[j];
        }
        __syncthreads();
    }
#pragma unroll
    for (int i = 0; i < 4; i++) {
        int m = m0 + tm * 4 + i;
        if (m >= M) continue;
#pragma unroll
        for (int j = 0; j < 4; j++) {
            int n = n0 + tn * 4 + j;
            if (n >= N) continue;
            float v = acc[i][j] + (bias ? bias[n] : 0.f);
            if (relu) v = fmaxf(v, 0.f);
            C[m * N + n] = v;
        }
    }
}

// ---------------- skinny GEMM: C[64,N] = A[64,K] @ W^T + bias ----------------
// W rows: row n<nsplit -> W0[n], else W1[n-nsplit]. 32-out x BT-batch tile.
template <int BT>
__global__ void __launch_bounds__(256) skinny_nt(
    const float* __restrict__ A, int K,
    const float* __restrict__ W0, const float* __restrict__ W1, int nsplit,
    const float* __restrict__ b0, const float* __restrict__ b1,
    float* __restrict__ C, int N)
{
    const int RB = BT / 8;
    __shared__ float sW[32][36];
    __shared__ float sA[BT][36];
    int tid = threadIdx.x, nl = tid & 31, wg = tid >> 5;
    int n0 = blockIdx.x * 32, bb = blockIdx.y * BT;
    int wr = tid >> 3, wkq = (tid & 7) * 4;
    float acc[RB];
#pragma unroll
    for (int r = 0; r < RB; r++) acc[r] = 0.f;

    for (int k0 = 0; k0 < K; k0 += 32) {
        int g = n0 + wr;
        const float* Wp = W0; int gr = g;
        if (g >= nsplit) { Wp = W1; gr = g - nsplit; }
#pragma unroll
        for (int q = 0; q < 4; q++) {
            int k = k0 + wkq + q;
            sW[wr][wkq + q] = (g < N && k < K) ? Wp[gr * K + k] : 0.f;
        }
#pragma unroll
        for (int r = 0; r < RB; r++) {
            int k = k0 + nl;
            sA[wg + r * 8][nl] = (k < K) ? A[(bb + wg + r * 8) * K + k] : 0.f;
        }
        __syncthreads();
#pragma unroll
        for (int k4 = 0; k4 < 8; k4++) {
            float4 wv = *reinterpret_cast<float4*>(&sW[nl][k4 * 4]);
#pragma unroll
            for (int r = 0; r < RB; r++) {
                float4 av = *reinterpret_cast<float4*>(&sA[wg + r * 8][k4 * 4]);
                acc[r] += av.x * wv.x + av.y * wv.y + av.z * wv.z + av.w * wv.w;
            }
        }
        __syncthreads();
    }
    int n = n0 + nl;
    if (n < N) {
        float bias = 0.f;
        if (n < nsplit) { if (b0) bias = b0[n]; }
        else            { if (b1) bias = b1[n - nsplit]; }
#pragma unroll
        for (int r = 0; r < RB; r++) C[(bb + wg + r * 8) * N + n] = acc[r] + bias;
    }
}

// ---------------- per-layer init: H1[:,0] = C0+P0, kdot[:,0] ----------------
__global__ void __launch_bounds__(256) k_init(
    const float* __restrict__ Hin, float* __restrict__ H1,
    const float* __restrict__ XI, const float* __restrict__ XP,
    const float* __restrict__ bhh_c, const float* __restrict__ bih_p,
    const float* __restrict__ wk, float* __restrict__ kdot)
{
    __shared__ float s_red[256];
    int b = blockIdx.x, tid = threadIdx.x;
    const float* xi = XI + b * NSEQ * G3;   // row 0
    const float* xp = XP + b * NSEQ * G3;
    const float* x0 = Hin + b * NSEQ * HID;
    float* h1 = H1 + b * NSEQ * HID;
    float kp = 0.f;
    for (int d = tid; d < HID; d += 256) {
        // C0 = gru(x=x0, h=0): gi = xi (has bih_c), gh = bhh_c
        float r  = sigf(xi[d] + bhh_c[d]);
        float z  = sigf(xi[300 + d] + bhh_c[300 + d]);
        float nn = tanhf(xi[600 + d] + r * bhh_c[600 + d]);
        float C0 = (1.f - z) * nn;
        // P0 = gru(x=0, h=x0): gi = bih_p, gh = xp (has bhh_p)
        float r2 = sigf(bih_p[d] + xp[d]);
        float z2 = sigf(bih_p[300 + d] + xp[300 + d]);
        float n2 = tanhf(bih_p[600 + d] + r2 * xp[600 + d]);
        float P0 = (1.f - z2) * n2 + z2 * x0[d];
        float h = C0 + P0;
        h1[d] = h;
        kp += h * wk[d];
    }
    float ks = blockReduceSum(kp, s_red);
    if (tid == 0) kdot[b * NSEQ] = ks;
}

// ---------------- per-step: apply prev update, then attention -> u ----------------
// i in [1..63]: (if i>=2 update row i-1 from g_M/g_G) then softmax/u for step i.
// i == 64: finalize (update row 63 only).
__global__ void __launch_bounds__(256) s1_kernel(
    const float* __restrict__ Hin, float* __restrict__ H1,
    const float* __restrict__ XI, const float* __restrict__ XP,
    const float* __restrict__ wq, const float* __restrict__ wk,
    const float* __restrict__ gatb, int layer,
    const int* __restrict__ spk, const int* __restrict__ start,
    float* __restrict__ kdot,
    const float* __restrict__ Mbuf, const float* __restrict__ Gbuf,
    float* __restrict__ ubuf, int i)
{
    __shared__ float s_red[256];
    __shared__ float s_w[64];
    __shared__ float s_sm[64];
    int b = blockIdx.x, tid = threadIdx.x;

    if (i >= 2) {
        int row = i - 1;
        const float* G  = Gbuf + b * 1800;
        const float* Mv = Mbuf + b * HID;
        const float* xi = XI + (b * NSEQ + row) * G3;
        const float* xp = XP + (b * NSEQ + row) * G3;
        const float* q  = Hin + (b * NSEQ + row) * HID;
        float* h1r = H1 + (b * NSEQ + row) * HID;
        float kp = 0.f;
        for (int d = tid; d < HID; d += 256) {
            float Md = Mv[d];
            // C = gru(x=Q, h=M): gi = xi, gh = G[0:900]
            float r  = sigf(xi[d] + G[d]);
            float z  = sigf(xi[300 + d] + G[300 + d]);
            float nn = tanhf(xi[600 + d] + r * G[600 + d]);
            float Cc = (1.f - z) * nn + z * Md;
            // P = gru(x=M, h=Q): gi = G[900:1800], gh = xp
            float r2 = sigf(G[900 + d] + xp[d]);
            float z2 = sigf(G[1200 + d] + xp[300 + d]);
            float n2 = tanhf(G[1500 + d] + r2 * xp[600 + d]);
            float Pp = (1.f - z2) * n2 + z2 * q[d];
            float h = Cc + Pp;
            h1r[d] = h;
            kp += h * wk[d];
        }
        float ks = blockReduceSum(kp, s_red);
        if (tid == 0) kdot[b * NSEQ + row] = ks;
        __syncthreads();
    }
    if (i > 63) return;

    // qdot
    const float* qrow = Hin + (b * NSEQ + i) * HID;
    float qp = 0.f;
    for (int d = tid; d < HID; d += 256) qp += qrow[d] * wq[d];
    float qd = blockReduceSum(qp, s_red);

    int st = start[b * NSEQ + i];
    int cnt = i - st;
    int spki = spk[b * NSEQ + i];
    float gb = gatb[layer];

    float aj = -1e30f;
    if (tid < cnt) aj = qd + kdot[b * NSEQ + st + tid] + gb;
    float mx = blockReduceMax(aj, s_red);
    float e = (tid < cnt) ? expf(aj - mx) : 0.f;
    float se = blockReduceSum(e, s_red);
    if (tid < cnt) {
        s_w[tid]  = e / se;
        s_sm[tid] = (spk[b * NSEQ + st + tid] == spki) ? 1.f : 0.f;
    }
    __syncthreads();

    // u0[e] = sum_j w*sm*H1[j,e]; u1[e] = sum_j w*(1-sm)*H1[j,e]
    for (int d = tid; d < 600; d += 256) {
        int ei = (d < 300) ? d : d - 300;
        float u0f = (d < 300) ? 1.f : 0.f;
        const float* base = H1 + (b * NSEQ + st) * HID + ei;
        float acc = 0.f;
        for (int j = 0; j < cnt; j++) {
            float m = s_sm[j];
            float sel = u0f * m + (1.f - u0f) * (1.f - m);
            acc += s_w[j] * sel * base[j * HID];
        }
        ubuf[b * 600 + d] = acc;
    }
}

// ---------------- Wr2 = [wr0 | wr1] ----------------
__global__ void k_wr2(const float* __restrict__ wr0, const float* __restrict__ wr1) {
    int idx = blockIdx.x * blockDim.x + threadIdx.x;
    if (idx < 300 * 600) {
        int d = idx / 600, e = idx - d * 600;
        g_Wr2[idx] = (e < 300) ? wr0[d * 300 + e] : wr1[d * 300 + (e - 300)];
    }
}

// ---------------- Hcat = [H0..H4, features] ----------------
__global__ void k_concat(const float* __restrict__ feat) {
    int r = blockIdx.x;  // 0..4095
    for (int c = threadIdx.x; c < KCAT; c += blockDim.x) {
        float v;
        if (c < 1500) {
            int seg = c / 300, off = c - seg * 300;
            v = g_H[seg * HSZ + r * HID + off];
        } else {
            v = feat[r * EMB + (c - 1500)];
        }
        g_Hcat[r * KCAT + c] = v;
    }
}

extern "C" void kernel_launch(void* const* d_in, const int* in_sizes, int n_in,
                              void* d_out, int out_size) {
    const float* features = (const float*)d_in[0];
    const int*   speakers = (const int*)d_in[1];
    const float* w_in   = (const float*)d_in[2];
    const float* b_in   = (const float*)d_in[3];
    const float* gat_wq = (const float*)d_in[4];
    const float* gat_wk = (const float*)d_in[5];
    const float* gat_b  = (const float*)d_in[6];
    const float* wr0    = (const float*)d_in[7];
    const float* wr1    = (const float*)d_in[8];
    const float* wih_c  = (const float*)d_in[9];
    const float* whh_c  = (const float*)d_in[10];
    const float* bih_c  = (const float*)d_in[11];
    const float* bhh_c  = (const float*)d_in[12];
    const float* wih_p  = (const float*)d_in[13];
    const float* whh_p  = (const float*)d_in[14];
    const float* bih_p  = (const float*)d_in[15];
    const float* bhh_p  = (const float*)d_in[16];
    const float* w1 = (const float*)d_in[17];
    const float* b1 = (const float*)d_in[18];
    const float* w2 = (const float*)d_in[19];
    const float* b2 = (const float*)d_in[20];
    const float* w3 = (const float*)d_in[21];
    const float* b3 = (const float*)d_in[22];

    float *H, *XIp, *XPp, *Wr2p, *up, *Mp, *Gp, *kdotp, *Hcatp, *h1p, *h2p;
    int *startp;
    cudaGetSymbolAddress((void**)&H,     g_H);
    cudaGetSymbolAddress((void**)&XIp,   g_XI);
    cudaGetSymbolAddress((void**)&XPp,   g_XP);
    cudaGetSymbolAddress((void**)&Wr2p,  g_Wr2);
    cudaGetSymbolAddress((void**)&up,    g_u);
    cudaGetSymbolAddress((void**)&Mp,    g_M);
    cudaGetSymbolAddress((void**)&Gp,    g_G);
    cudaGetSymbolAddress((void**)&kdotp, g_kdot);
    cudaGetSymbolAddress((void**)&startp,g_start);
    cudaGetSymbolAddress((void**)&Hcatp, g_Hcat);
    cudaGetSymbolAddress((void**)&h1p,   g_h1);
    cudaGetSymbolAddress((void**)&h2p,   g_h2);

    const int MROWS = BATCH * NSEQ;   // 4096

    k_start<<<BATCH, NSEQ>>>(speakers, startp);

    // H0 = relu(features @ w_in.T + b_in)
    gemm_nt<<<dim3((HID + 63) / 64, MROWS / 64), 256>>>(
        features, w_in, b_in, H, MROWS, HID, EMB, 1);

    for (int l = 0; l < 4; l++) {
        const float* Hin = H + l * HSZ;
        float* H1 = H + (l + 1) * HSZ;
        const float* wih_c_l = wih_c + l * G3 * HID;
        const float* whh_c_l = whh_c + l * G3 * HID;
        const float* wih_p_l = wih_p + l * G3 * HID;
        const float* whh_p_l = whh_p + l * G3 * HID;
        const float* bih_c_l = bih_c + l * G3;
        const float* bhh_c_l = bhh_c + l * G3;
        const float* bih_p_l = bih_p + l * G3;
        const float* bhh_p_l = bhh_p + l * G3;
        const float* wq_l = gat_wq + l * HID;
        const float* wk_l = gat_wk + l * HID;

        // XI = Hin @ wih_c.T + bih_c ;  XP = Hin @ whh_p.T + bhh_p
        gemm_nt<<<dim3((G3 + 63) / 64, MROWS / 64), 256>>>(
            Hin, wih_c_l, bih_c_l, XIp, MROWS, G3, HID, 0);
        gemm_nt<<<dim3((G3 + 63) / 64, MROWS / 64), 256>>>(
            Hin, whh_p_l, bhh_p_l, XPp, MROWS, G3, HID, 0);
        k_wr2<<<(300 * 600 + 255) / 256, 256>>>(wr0 + l * HID * HID, wr1 + l * HID * HID);

        k_init<<<BATCH, 256>>>(Hin, H1, XIp, XPp, bhh_c_l, bih_p_l, wk_l, kdotp);

        for (int i = 1; i <= 63; i++) {
            s1_kernel<<<BATCH, 256>>>(Hin, H1, XIp, XPp, wq_l, wk_l, gat_b, l,
                                      speakers, startp, kdotp, Mp, Gp, up, i);
            // M = u @ Wr2^T  (64 x 300, K=600)
            skinny_nt<8><<<dim3(10, 8), 256>>>(
                up, 600, Wr2p, (const float*)nullptr, 300,
                (const float*)nullptr, (const float*)nullptr, Mp, 300);
            // G = M @ [whh_c ; wih_p]^T + [bhh_c ; bih_p]  (64 x 1800, K=300)
            skinny_nt<32><<<dim3(57, 2), 256>>>(
                Mp, 300, whh_c_l, wih_p_l, 900, bhh_c_l, bih_p_l, Gp, 1800);
        }
        // finalize: apply update for row 63
        s1_kernel<<<BATCH, 256>>>(Hin, H1, XIp, XPp, wq_l, wk_l, gat_b, l,
                                  speakers, startp, kdotp, Mp, Gp, up, 64);
    }

    k_concat<<<MROWS, 256>>>(features);

    gemm_nt<<<dim3((HID + 63) / 64, MROWS / 64), 256>>>(
        Hcatp, w1, b1, h1p, MROWS, HID, KCAT, 1);
    gemm_nt<<<dim3((HID + 63) / 64, MROWS / 64), 256>>>(
        h1p, w2, b2, h2p, MROWS, HID, HID, 1);
    gemm_nt<<<dim3(1, MROWS / 64), 256>>>(
        h2p, w3, b3, (float*)d_out, MROWS, 7, HID, 0);
}

// round 5
// speedup vs baseline: 1.2273x; 1.1987x over previous
#include <cuda_runtime.h>
#include <math.h>

#define HID   300
#define G3    900
#define NSEQ  64
#define BATCH 64
#define EMB   1024
#define KCAT  2524
#define HSZ   (BATCH*NSEQ*HID)
#define NCTA  132
#define GEFFN 2100

// ---------------- device scratch (no cudaMalloc allowed) ----------------
__device__ float g_H[5 * HSZ];                 // H0..H4
__device__ float g_XI[BATCH * NSEQ * G3];      // Q@wih_c.T + bih_c (current layer)
__device__ float g_XP[BATCH * NSEQ * G3];      // Q@whh_p.T + bhh_p
__device__ float g_Wr2T[600 * HID];            // Wr2^T : [600,300]
__device__ float g_WG[1800 * HID];             // [whh_c ; wih_p]
__device__ float g_Geff[GEFFN * 600];          // rows 0..1799: WG@Wr2, rows 1800..2099: Wr2
__device__ float g_u[BATCH * 600];             // [u0;u1]
__device__ float g_G2[BATCH * GEFFN];          // per-step gates (0..1799 w/ bias) + M (1800..2099)
__device__ int   g_start[BATCH * NSEQ];
__device__ float g_Hcat[BATCH * NSEQ * KCAT];
__device__ float g_h1[BATCH * NSEQ * HID];
__device__ float g_h2[BATCH * NSEQ * HID];

// grid barrier state
__device__ unsigned g_cnt = 0;
__device__ unsigned g_gen = 0;

__device__ __forceinline__ float sigf(float x) { return 1.0f / (1.0f + expf(-x)); }

__device__ __forceinline__ float blockReduceSum(float v, float* s) {
    int tid = threadIdx.x;
    s[tid] = v; __syncthreads();
    for (int o = 128; o > 0; o >>= 1) { if (tid < o) s[tid] += s[tid + o]; __syncthreads(); }
    float r = s[0]; __syncthreads(); return r;
}
__device__ __forceinline__ float blockReduceMax(float v, float* s) {
    int tid = threadIdx.x;
    s[tid] = v; __syncthreads();
    for (int o = 128; o > 0; o >>= 1) { if (tid < o) s[tid] = fmaxf(s[tid], s[tid + o]); __syncthreads(); }
    float r = s[0]; __syncthreads(); return r;
}

// ---------------- start index per (b,i) ----------------
__global__ void k_start(const int* __restrict__ spk, int* __restrict__ start) {
    int b = blockIdx.x, i = threadIdx.x;
    int s = spk[b * NSEQ + i];
    int last = -1;
    for (int j = 0; j < i; j++)
        if (spk[b * NSEQ + j] == s) last = j;
    start[b * NSEQ + i] = last > 0 ? last : 0;
}

// ---------------- generic C = A@B^T + bias (opt relu) ----------------
__global__ void __launch_bounds__(256) gemm_nt(
    const float* __restrict__ A, const float* __restrict__ B,
    const float* __restrict__ bias, float* __restrict__ C,
    int M, int N, int K, int relu)
{
    __shared__ float sA[16][65];
    __shared__ float sB[16][65];
    int tid = threadIdx.x;
    int m0 = blockIdx.y * 64, n0 = blockIdx.x * 64;
    int tm = tid >> 4, tn = tid & 15;
    int lr = tid >> 2, lk = (tid & 3) * 4;
    float acc[4][4];
#pragma unroll
    for (int i = 0; i < 4; i++)
#pragma unroll
        for (int j = 0; j < 4; j++) acc[i][j] = 0.f;

    for (int k0 = 0; k0 < K; k0 += 16) {
#pragma unroll
        for (int q = 0; q < 4; q++) {
            int k = k0 + lk + q;
            sA[lk + q][lr] = (k < K && (m0 + lr) < M) ? A[(m0 + lr) * K + k] : 0.f;
            sB[lk + q][lr] = (k < K && (n0 + lr) < N) ? B[(n0 + lr) * K + k] : 0.f;
        }
        __syncthreads();
#pragma unroll
        for (int kk = 0; kk < 16; kk++) {
            float a[4], bv[4];
#pragma unroll
            for (int i = 0; i < 4; i++) { a[i] = sA[kk][tm * 4 + i]; bv[i] = sB[kk][tn * 4 + i]; }
#pragma unroll
            for (int i = 0; i < 4; i++)
#pragma unroll
                for (int j = 0; j < 4; j++) acc[i][j] += a[i] * bv[j];
        }
        __syncthreads();
    }
#pragma unroll
    for (int i = 0; i < 4; i++) {
        int m = m0 + tm * 4 + i;
        if (m >= M) continue;
#pragma unroll
        for (int j = 0; j < 4; j++) {
            int n = n0 + tn * 4 + j;
            if (n >= N) continue;
            float v = acc[i][j] + (bias ? bias[n] : 0.f);
            if (relu) v = fmaxf(v, 0.f);
            C[m * N + n] = v;
        }
    }
}

// ---------------- Wr2T + Geff bottom rows ----------------
__global__ void k_wr2(const float* __restrict__ wr0, const float* __restrict__ wr1) {
    int idx = blockIdx.x * blockDim.x + threadIdx.x;
    if (idx < 300 * 600) {
        int d = idx / 600, e = idx - d * 600;
        float v = (e < 300) ? wr0[d * 300 + e] : wr1[d * 300 + (e - 300)];
        g_Wr2T[e * 300 + d] = v;
        g_Geff[(1800 + d) * 600 + e] = v;
    }
}

// ---------------- WG = [whh_c ; wih_p] ----------------
__global__ void k_wg(const float* __restrict__ whh_c, const float* __restrict__ wih_p) {
    int idx = blockIdx.x * blockDim.x + threadIdx.x;
    if (idx < 1800 * 300) {
        int n = idx / 300, d = idx - n * 300;
        g_WG[idx] = (n < 900) ? whh_c[n * 300 + d] : wih_p[(n - 900) * 300 + d];
    }
}

// ---------------- persistent per-layer scan kernel ----------------
__global__ void __launch_bounds__(256, 1) persist_layer(
    const float* __restrict__ Hin, float* __restrict__ H1,
    const float* __restrict__ XI, const float* __restrict__ XP,
    const float* __restrict__ wq, const float* __restrict__ wk,
    const float* __restrict__ gatb, int layer,
    const int* __restrict__ spk, const int* __restrict__ start,
    const float* __restrict__ bhh_c, const float* __restrict__ bih_p,
    const float* __restrict__ Geff, float* __restrict__ u,
    float* __restrict__ G2)
{
    __shared__ float sW[16 * 604];
    __shared__ float s_red[256];
    __shared__ float s_w[64];
    __shared__ float s_sm[64];
    __shared__ float s_kdot[64];

    const int tid = threadIdx.x;
    const int cta = blockIdx.x;
    const int b = cta;
    const int n0 = cta * 16;

    // load persistent weight slice (once per layer)
    for (int idx = tid; idx < 16 * 600; idx += 256) {
        int c = idx / 600, k = idx - c * 600;
        int n = n0 + c;
        sW[c * 604 + k] = (n < GEFFN) ? Geff[n * 600 + k] : 0.f;
    }

    const int cB = tid & 15, bgB = tid >> 4;
    const int nB = n0 + cB;
    float biasv = 0.f;
    if (nB < 900) biasv = bhh_c[nB];
    else if (nB < 1800) biasv = bih_p[nB - 900];

    unsigned barBase = 0, barNum = 0;
    if (tid == 0) barBase = *(volatile unsigned*)&g_gen;

    const float gb = gatb[layer];

    // ---- per-batch init: H1 row 0 = C0 + P0, kdot[0] ----
    if (cta < 64) {
        const float* xi = XI + b * NSEQ * G3;
        const float* xp = XP + b * NSEQ * G3;
        const float* x0 = Hin + b * NSEQ * HID;
        float* h1 = H1 + b * NSEQ * HID;
        float kp = 0.f;
        for (int d = tid; d < HID; d += 256) {
            float r  = sigf(xi[d] + bhh_c[d]);
            float z  = sigf(xi[300 + d] + bhh_c[300 + d]);
            float nn = tanhf(xi[600 + d] + r * bhh_c[600 + d]);
            float C0 = (1.f - z) * nn;
            float r2 = sigf(bih_p[d] + xp[d]);
            float z2 = sigf(bih_p[300 + d] + xp[300 + d]);
            float n2 = tanhf(bih_p[600 + d] + r2 * xp[600 + d]);
            float P0 = (1.f - z2) * n2 + z2 * x0[d];
            float h = C0 + P0;
            h1[d] = h;
            kp += h * wk[d];
        }
        float ks = blockReduceSum(kp, s_red);
        if (tid == 0) s_kdot[0] = ks;
    }
    __syncthreads();

    for (int i = 1; i <= 63; i++) {
        // ================= phase A: GRU update of row i-1 + attention -> u =================
        if (cta < 64) {
            if (i >= 2) {
                int row = i - 1;
                const float* Gp = G2 + b * GEFFN;
                const float* xi = XI + (b * NSEQ + row) * G3;
                const float* xp = XP + (b * NSEQ + row) * G3;
                const float* q  = Hin + (b * NSEQ + row) * HID;
                float* h1r = H1 + (b * NSEQ + row) * HID;
                float kp = 0.f;
                for (int d = tid; d < HID; d += 256) {
                    float Md = __ldcg(Gp + 1800 + d);
                    float r  = sigf(xi[d]       + __ldcg(Gp + d));
                    float z  = sigf(xi[300 + d] + __ldcg(Gp + 300 + d));
                    float nn = tanhf(xi[600 + d] + r * __ldcg(Gp + 600 + d));
                    float Cc = (1.f - z) * nn + z * Md;
                    float r2 = sigf(__ldcg(Gp + 900 + d)  + xp[d]);
                    float z2 = sigf(__ldcg(Gp + 1200 + d) + xp[300 + d]);
                    float n2 = tanhf(__ldcg(Gp + 1500 + d) + r2 * xp[600 + d]);
                    float Pp = (1.f - z2) * n2 + z2 * q[d];
                    float h = Cc + Pp;
                    h1r[d] = h;
                    kp += h * wk[d];
                }
                float ks = blockReduceSum(kp, s_red);
                if (tid == 0) s_kdot[row] = ks;
                __syncthreads();
            }
            // attention for step i
            const float* qrow = Hin + (b * NSEQ + i) * HID;
            float qp = 0.f;
            for (int d = tid; d < HID; d += 256) qp += qrow[d] * wq[d];
            float qd = blockReduceSum(qp, s_red);

            int st = start[b * NSEQ + i];
            int cnt = i - st;
            int spki = spk[b * NSEQ + i];

            float aj = -1e30f;
            if (tid < cnt) aj = qd + s_kdot[st + tid] + gb;
            float mx = blockReduceMax(aj, s_red);
            float e = (tid < cnt) ? expf(aj - mx) : 0.f;
            float se = blockReduceSum(e, s_red);
            if (tid < cnt) {
                s_w[tid]  = e / se;
                s_sm[tid] = (spk[b * NSEQ + st + tid] == spki) ? 1.f : 0.f;
            }
            __syncthreads();
            for (int d = tid; d < 600; d += 256) {
                int ei = (d < 300) ? d : d - 300;
                float u0f = (d < 300) ? 1.f : 0.f;
                const float* base = H1 + (b * NSEQ + st) * HID + ei;
                float acc = 0.f;
                for (int j = 0; j < cnt; j++) {
                    float m = s_sm[j];
                    float sel = u0f * m + (1.f - u0f) * (1.f - m);
                    acc += s_w[j] * sel * base[j * HID];
                }
                u[b * 600 + d] = acc;
            }
            __syncthreads();
        }
        // ---- barrier 1: u ready ----
        {
            __threadfence();
            __syncthreads();
            barNum++;
            if (tid == 0) {
                if (atomicAdd(&g_cnt, 1) == (unsigned)(gridDim.x - 1)) {
                    g_cnt = 0;
                    __threadfence();
                    atomicExch(&g_gen, barBase + barNum);
                } else {
                    while (*(volatile unsigned*)&g_gen != barBase + barNum) __nanosleep(32);
                }
            }
            __syncthreads();
        }
        // ================= phase B: G2 = u @ Geff^T + bias =================
        {
            float acc0 = 0.f, acc1 = 0.f, acc2 = 0.f, acc3 = 0.f;
            const float4* w4  = (const float4*)(sW + cB * 604);
            const float4* up0 = (const float4*)(u + (bgB * 4 + 0) * 600);
            const float4* up1 = (const float4*)(u + (bgB * 4 + 1) * 600);
            const float4* up2 = (const float4*)(u + (bgB * 4 + 2) * 600);
            const float4* up3 = (const float4*)(u + (bgB * 4 + 3) * 600);
#pragma unroll 5
            for (int k4 = 0; k4 < 150; k4++) {
                float4 w  = w4[k4];
                float4 a0 = __ldcg(up0 + k4);
                float4 a1 = __ldcg(up1 + k4);
                float4 a2 = __ldcg(up2 + k4);
                float4 a3 = __ldcg(up3 + k4);
                acc0 += w.x * a0.x + w.y * a0.y + w.z * a0.z + w.w * a0.w;
                acc1 += w.x * a1.x + w.y * a1.y + w.z * a1.z + w.w * a1.w;
                acc2 += w.x * a2.x + w.y * a2.y + w.z * a2.z + w.w * a2.w;
                acc3 += w.x * a3.x + w.y * a3.y + w.z * a3.z + w.w * a3.w;
            }
            if (nB < GEFFN) {
                G2[(bgB * 4 + 0) * GEFFN + nB] = acc0 + biasv;
                G2[(bgB * 4 + 1) * GEFFN + nB] = acc1 + biasv;
                G2[(bgB * 4 + 2) * GEFFN + nB] = acc2 + biasv;
                G2[(bgB * 4 + 3) * GEFFN + nB] = acc3 + biasv;
            }
        }
        // ---- barrier 2: G2 ready ----
        {
            __threadfence();
            __syncthreads();
            barNum++;
            if (tid == 0) {
                if (atomicAdd(&g_cnt, 1) == (unsigned)(gridDim.x - 1)) {
                    g_cnt = 0;
                    __threadfence();
                    atomicExch(&g_gen, barBase + barNum);
                } else {
                    while (*(volatile unsigned*)&g_gen != barBase + barNum) __nanosleep(32);
                }
            }
            __syncthreads();
        }
    }

    // ---- final GRU update: row 63 ----
    if (cta < 64) {
        int row = 63;
        const float* Gp = G2 + b * GEFFN;
        const float* xi = XI + (b * NSEQ + row) * G3;
        const float* xp = XP + (b * NSEQ + row) * G3;
        const float* q  = Hin + (b * NSEQ + row) * HID;
        float* h1r = H1 + (b * NSEQ + row) * HID;
        for (int d = tid; d < HID; d += 256) {
            float Md = __ldcg(Gp + 1800 + d);
            float r  = sigf(xi[d]       + __ldcg(Gp + d));
            float z  = sigf(xi[300 + d] + __ldcg(Gp + 300 + d));
            float nn = tanhf(xi[600 + d] + r * __ldcg(Gp + 600 + d));
            float Cc = (1.f - z) * nn + z * Md;
            float r2 = sigf(__ldcg(Gp + 900 + d)  + xp[d]);
            float z2 = sigf(__ldcg(Gp + 1200 + d) + xp[300 + d]);
            float n2 = tanhf(__ldcg(Gp + 1500 + d) + r2 * xp[600 + d]);
            float Pp = (1.f - z2) * n2 + z2 * q[d];
            h1r[d] = Cc + Pp;
        }
    }
}

// ---------------- Hcat = [H0..H4, features] ----------------
__global__ void k_concat(const float* __restrict__ feat) {
    int r = blockIdx.x;  // 0..4095
    for (int c = threadIdx.x; c < KCAT; c += blockDim.x) {
        float v;
        if (c < 1500) {
            int seg = c / 300, off = c - seg * 300;
            v = g_H[seg * HSZ + r * HID + off];
        } else {
            v = feat[r * EMB + (c - 1500)];
        }
        g_Hcat[r * KCAT + c] = v;
    }
}

extern "C" void kernel_launch(void* const* d_in, const int* in_sizes, int n_in,
                              void* d_out, int out_size) {
    const float* features = (const float*)d_in[0];
    const int*   speakers = (const int*)d_in[1];
    const float* w_in   = (const float*)d_in[2];
    const float* b_in   = (const float*)d_in[3];
    const float* gat_wq = (const float*)d_in[4];
    const float* gat_wk = (const float*)d_in[5];
    const float* gat_b  = (const float*)d_in[6];
    const float* wr0    = (const float*)d_in[7];
    const float* wr1    = (const float*)d_in[8];
    const float* wih_c  = (const float*)d_in[9];
    const float* whh_c  = (const float*)d_in[10];
    const float* bih_c  = (const float*)d_in[11];
    const float* bhh_c  = (const float*)d_in[12];
    const float* wih_p  = (const float*)d_in[13];
    const float* whh_p  = (const float*)d_in[14];
    const float* bih_p  = (const float*)d_in[15];
    const float* bhh_p  = (const float*)d_in[16];
    const float* w1 = (const float*)d_in[17];
    const float* b1 = (const float*)d_in[18];
    const float* w2 = (const float*)d_in[19];
    const float* b2 = (const float*)d_in[20];
    const float* w3 = (const float*)d_in[21];
    const float* b3 = (const float*)d_in[22];

    float *H, *XIp, *XPp, *Wr2Tp, *WGp, *Geffp, *up, *G2p, *Hcatp, *h1p, *h2p;
    int *startp;
    cudaGetSymbolAddress((void**)&H,     g_H);
    cudaGetSymbolAddress((void**)&XIp,   g_XI);
    cudaGetSymbolAddress((void**)&XPp,   g_XP);
    cudaGetSymbolAddress((void**)&Wr2Tp, g_Wr2T);
    cudaGetSymbolAddress((void**)&WGp,   g_WG);
    cudaGetSymbolAddress((void**)&Geffp, g_Geff);
    cudaGetSymbolAddress((void**)&up,    g_u);
    cudaGetSymbolAddress((void**)&G2p,   g_G2);
    cudaGetSymbolAddress((void**)&startp,g_start);
    cudaGetSymbolAddress((void**)&Hcatp, g_Hcat);
    cudaGetSymbolAddress((void**)&h1p,   g_h1);
    cudaGetSymbolAddress((void**)&h2p,   g_h2);

    const int MROWS = BATCH * NSEQ;   // 4096

    k_start<<<BATCH, NSEQ>>>(speakers, startp);

    // H0 = relu(features @ w_in.T + b_in)
    gemm_nt<<<dim3((HID + 63) / 64, MROWS / 64), 256>>>(
        features, w_in, b_in, H, MROWS, HID, EMB, 1);

    for (int l = 0; l < 4; l++) {
        const float* Hin = H + l * HSZ;
        float* H1 = H + (l + 1) * HSZ;
        const float* wih_c_l = wih_c + l * G3 * HID;
        const float* whh_c_l = whh_c + l * G3 * HID;
        const float* wih_p_l = wih_p + l * G3 * HID;
        const float* whh_p_l = whh_p + l * G3 * HID;
        const float* bih_c_l = bih_c + l * G3;
        const float* bhh_c_l = bhh_c + l * G3;
        const float* bih_p_l = bih_p + l * G3;
        const float* bhh_p_l = bhh_p + l * G3;
        const float* wq_l = gat_wq + l * HID;
        const float* wk_l = gat_wk + l * HID;

        // XI = Hin @ wih_c.T + bih_c ;  XP = Hin @ whh_p.T + bhh_p
        gemm_nt<<<dim3((G3 + 63) / 64, MROWS / 64), 256>>>(
            Hin, wih_c_l, bih_c_l, XIp, MROWS, G3, HID, 0);
        gemm_nt<<<dim3((G3 + 63) / 64, MROWS / 64), 256>>>(
            Hin, whh_p_l, bhh_p_l, XPp, MROWS, G3, HID, 0);

        // Geff: bottom rows (Wr2) + Wr2T
        k_wr2<<<(300 * 600 + 255) / 256, 256>>>(wr0 + l * HID * HID, wr1 + l * HID * HID);
        // WG = [whh_c ; wih_p]
        k_wg<<<(1800 * 300 + 255) / 256, 256>>>(whh_c_l, wih_p_l);
        // Geff top rows = WG @ Wr2  (via gemm_nt with Wr2T)
        gemm_nt<<<dim3((600 + 63) / 64, (1800 + 63) / 64), 256>>>(
            WGp, Wr2Tp, (const float*)nullptr, Geffp, 1800, 600, 300, 0);

        // whole sequential scan for this layer in one persistent kernel
        persist_layer<<<NCTA, 256>>>(
            Hin, H1, XIp, XPp, wq_l, wk_l, gat_b, l,
            speakers, startp, bhh_c_l, bih_p_l, Geffp, up, G2p);
    }

    k_concat<<<MROWS, 256>>>(features);

    gemm_nt<<<dim3((HID + 63) / 64, MROWS / 64), 256>>>(
        Hcatp, w1, b1, h1p, MROWS, HID, KCAT, 1);
    gemm_nt<<<dim3((HID + 63) / 64, MROWS / 64), 256>>>(
        h1p, w2, b2, h2p, MROWS, HID, HID, 1);
    gemm_nt<<<dim3(1, MROWS / 64), 256>>>(
        h2p, w3, b3, (float*)d_out, MROWS, 7, HID, 0);
}

// round 6
// speedup vs baseline: 1.2319x; 1.0038x over previous
#include <cuda_runtime.h>
#include <math.h>

#define HID   300
#define G3    900
#define NSEQ  64
#define BATCH 64
#define EMB   1024
#define KCAT  2524
#define HSZ   (BATCH*NSEQ*HID)
#define NCTA  132
#define GEFFN 2100

// ---------------- device scratch (no cudaMalloc allowed) ----------------
__device__ float g_H[5 * HSZ];                 // H0..H4
__device__ float g_XI[BATCH * NSEQ * G3];      // Q@wih_c.T + bih_c (current layer)
__device__ float g_XP[BATCH * NSEQ * G3];      // Q@whh_p.T + bhh_p
__device__ float g_Wr2T[600 * HID];            // Wr2^T : [600,300]
__device__ float g_WG[1800 * HID];             // [whh_c ; wih_p]
__device__ float g_Geff[GEFFN * 600];          // rows 0..1799: WG@Wr2, rows 1800..2099: Wr2
__device__ float g_u[BATCH * 600];             // [u0;u1]
__device__ float g_G2[BATCH * GEFFN];          // per-step gates (0..1799 w/ bias) + M (1800..2099)
__device__ int   g_start[BATCH * NSEQ];
__device__ float g_Hcat[BATCH * NSEQ * KCAT];
__device__ float g_h1[BATCH * NSEQ * HID];
__device__ float g_h2[BATCH * NSEQ * HID];

// grid barrier state
__device__ unsigned g_cnt = 0;
__device__ unsigned g_gen = 0;

__device__ __forceinline__ float sigf(float x) { return 1.0f / (1.0f + expf(-x)); }

__device__ __forceinline__ float blockReduceSum(float v, float* s) {
    int tid = threadIdx.x;
    s[tid] = v; __syncthreads();
    for (int o = 128; o > 0; o >>= 1) { if (tid < o) s[tid] += s[tid + o]; __syncthreads(); }
    float r = s[0]; __syncthreads(); return r;
}
__device__ __forceinline__ float blockReduceMax(float v, float* s) {
    int tid = threadIdx.x;
    s[tid] = v; __syncthreads();
    for (int o = 128; o > 0; o >>= 1) { if (tid < o) s[tid] = fmaxf(s[tid], s[tid + o]); __syncthreads(); }
    float r = s[0]; __syncthreads(); return r;
}

// ---------------- start index per (b,i) ----------------
__global__ void k_start(const int* __restrict__ spk, int* __restrict__ start) {
    int b = blockIdx.x, i = threadIdx.x;
    int s = spk[b * NSEQ + i];
    int last = -1;
    for (int j = 0; j < i; j++)
        if (spk[b * NSEQ + j] == s) last = j;
    start[b * NSEQ + i] = last > 0 ? last : 0;
}

// ---------------- generic C = A@B^T + bias (opt relu) ----------------
__global__ void __launch_bounds__(256) gemm_nt(
    const float* __restrict__ A, const float* __restrict__ B,
    const float* __restrict__ bias, float* __restrict__ C,
    int M, int N, int K, int relu)
{
    __shared__ float sA[16][65];
    __shared__ float sB[16][65];
    int tid = threadIdx.x;
    int m0 = blockIdx.y * 64, n0 = blockIdx.x * 64;
    int tm = tid >> 4, tn = tid & 15;
    int lr = tid >> 2, lk = (tid & 3) * 4;
    float acc[4][4];
#pragma unroll
    for (int i = 0; i < 4; i++)
#pragma unroll
        for (int j = 0; j < 4; j++) acc[i][j] = 0.f;

    for (int k0 = 0; k0 < K; k0 += 16) {
#pragma unroll
        for (int q = 0; q < 4; q++) {
            int k = k0 + lk + q;
            sA[lk + q][lr] = (k < K && (m0 + lr) < M) ? A[(m0 + lr) * K + k] : 0.f;
            sB[lk + q][lr] = (k < K && (n0 + lr) < N) ? B[(n0 + lr) * K + k] : 0.f;
        }
        __syncthreads();
#pragma unroll
        for (int kk = 0; kk < 16; kk++) {
            float a[4], bv[4];
#pragma unroll
            for (int i = 0; i < 4; i++) { a[i] = sA[kk][tm * 4 + i]; bv[i] = sB[kk][tn * 4 + i]; }
#pragma unroll
            for (int i = 0; i < 4; i++)
#pragma unroll
                for (int j = 0; j < 4; j++) acc[i][j] += a[i] * bv[j];
        }
        __syncthreads();
    }
#pragma unroll
    for (int i = 0; i < 4; i++) {
        int m = m0 + tm * 4 + i;
        if (m >= M) continue;
#pragma unroll
        for (int j = 0; j < 4; j++) {
            int n = n0 + tn * 4 + j;
            if (n >= N) continue;
            float v = acc[i][j] + (bias ? bias[n] : 0.f);
            if (relu) v = fmaxf(v, 0.f);
            C[m * N + n] = v;
        }
    }
}

// ---------------- Wr2T + Geff bottom rows ----------------
__global__ void k_wr2(const float* __restrict__ wr0, const float* __restrict__ wr1) {
    int idx = blockIdx.x * blockDim.x + threadIdx.x;
    if (idx < 300 * 600) {
        int d = idx / 600, e = idx - d * 600;
        float v = (e < 300) ? wr0[d * 300 + e] : wr1[d * 300 + (e - 300)];
        g_Wr2T[e * 300 + d] = v;
        g_Geff[(1800 + d) * 600 + e] = v;
    }
}

// ---------------- WG = [whh_c ; wih_p] ----------------
__global__ void k_wg(const float* __restrict__ whh_c, const float* __restrict__ wih_p) {
    int idx = blockIdx.x * blockDim.x + threadIdx.x;
    if (idx < 1800 * 300) {
        int n = idx / 300, d = idx - n * 300;
        g_WG[idx] = (n < 900) ? whh_c[n * 300 + d] : wih_p[(n - 900) * 300 + d];
    }
}

// ---------------- persistent per-layer scan kernel ----------------
__global__ void __launch_bounds__(256, 1) persist_layer(
    const float* __restrict__ Hin, float* __restrict__ H1,
    const float* __restrict__ XI, const float* __restrict__ XP,
    const float* __restrict__ wq, const float* __restrict__ wk,
    const float* __restrict__ gatb, int layer,
    const int* __restrict__ spk, const int* __restrict__ start,
    const float* __restrict__ bhh_c, const float* __restrict__ bih_p,
    const float* __restrict__ Geff, float* __restrict__ u,
    float* __restrict__ G2)
{
    __shared__ float sW[16 * 604];
    __shared__ float s_red[256];
    __shared__ float s_w[64];
    __shared__ float s_sm[64];
    __shared__ float s_kdot[64];

    const int tid = threadIdx.x;
    const int cta = blockIdx.x;
    const int b = cta;
    const int n0 = cta * 16;

    // load persistent weight slice (once per layer)
    for (int idx = tid; idx < 16 * 600; idx += 256) {
        int c = idx / 600, k = idx - c * 600;
        int n = n0 + c;
        sW[c * 604 + k] = (n < GEFFN) ? Geff[n * 600 + k] : 0.f;
    }

    const int cB = tid & 15, bgB = tid >> 4;
    const int nB = n0 + cB;
    float biasv = 0.f;
    if (nB < 900) biasv = bhh_c[nB];
    else if (nB < 1800) biasv = bih_p[nB - 900];

    unsigned barBase = 0, barNum = 0;
    if (tid == 0) barBase = *(volatile unsigned*)&g_gen;

    const float gb = gatb[layer];

    // ---- per-batch init: H1 row 0 = C0 + P0, kdot[0] ----
    if (cta < 64) {
        const float* xi = XI + b * NSEQ * G3;
        const float* xp = XP + b * NSEQ * G3;
        const float* x0 = Hin + b * NSEQ * HID;
        float* h1 = H1 + b * NSEQ * HID;
        float kp = 0.f;
        for (int d = tid; d < HID; d += 256) {
            float r  = sigf(xi[d] + bhh_c[d]);
            float z  = sigf(xi[300 + d] + bhh_c[300 + d]);
            float nn = tanhf(xi[600 + d] + r * bhh_c[600 + d]);
            float C0 = (1.f - z) * nn;
            float r2 = sigf(bih_p[d] + xp[d]);
            float z2 = sigf(bih_p[300 + d] + xp[300 + d]);
            float n2 = tanhf(bih_p[600 + d] + r2 * xp[600 + d]);
            float P0 = (1.f - z2) * n2 + z2 * x0[d];
            float h = C0 + P0;
            h1[d] = h;
            kp += h * wk[d];
        }
        float ks = blockReduceSum(kp, s_red);
        if (tid == 0) s_kdot[0] = ks;
    }
    __syncthreads();

    for (int i = 1; i <= 63; i++) {
        // ================= phase A: GRU update of row i-1 + attention -> u =================
        if (cta < 64) {
            if (i >= 2) {
                int row = i - 1;
                const float* Gp = G2 + b * GEFFN;
                const float* xi = XI + (b * NSEQ + row) * G3;
                const float* xp = XP + (b * NSEQ + row) * G3;
                const float* q  = Hin + (b * NSEQ + row) * HID;
                float* h1r = H1 + (b * NSEQ + row) * HID;
                float kp = 0.f;
                for (int d = tid; d < HID; d += 256) {
                    float Md = __ldcg(Gp + 1800 + d);
                    float r  = sigf(xi[d]       + __ldcg(Gp + d));
                    float z  = sigf(xi[300 + d] + __ldcg(Gp + 300 + d));
                    float nn = tanhf(xi[600 + d] + r * __ldcg(Gp + 600 + d));
                    float Cc = (1.f - z) * nn + z * Md;
                    float r2 = sigf(__ldcg(Gp + 900 + d)  + xp[d]);
                    float z2 = sigf(__ldcg(Gp + 1200 + d) + xp[300 + d]);
                    float n2 = tanhf(__ldcg(Gp + 1500 + d) + r2 * xp[600 + d]);
                    float Pp = (1.f - z2) * n2 + z2 * q[d];
                    float h = Cc + Pp;
                    h1r[d] = h;
                    kp += h * wk[d];
                }
                float ks = blockReduceSum(kp, s_red);
                if (tid == 0) s_kdot[row] = ks;
                __syncthreads();
            }
            // attention for step i
            const float* qrow = Hin + (b * NSEQ + i) * HID;
            float qp = 0.f;
            for (int d = tid; d < HID; d += 256) qp += qrow[d] * wq[d];
            float qd = blockReduceSum(qp, s_red);

            int st = start[b * NSEQ + i];
            int cnt = i - st;
            int spki = spk[b * NSEQ + i];

            float aj = -1e30f;
            if (tid < cnt) aj = qd + s_kdot[st + tid] + gb;
            float mx = blockReduceMax(aj, s_red);
            float e = (tid < cnt) ? expf(aj - mx) : 0.f;
            float se = blockReduceSum(e, s_red);
            if (tid < cnt) {
                s_w[tid]  = e / se;
                s_sm[tid] = (spk[b * NSEQ + st + tid] == spki) ? 1.f : 0.f;
            }
            __syncthreads();
            for (int d = tid; d < 600; d += 256) {
                int ei = (d < 300) ? d : d - 300;
                float u0f = (d < 300) ? 1.f : 0.f;
                const float* base = H1 + (b * NSEQ + st) * HID + ei;
                float acc = 0.f;
                for (int j = 0; j < cnt; j++) {
                    float m = s_sm[j];
                    float sel = u0f * m + (1.f - u0f) * (1.f - m);
                    acc += s_w[j] * sel * base[j * HID];
                }
                u[b * 600 + d] = acc;
            }
            __syncthreads();
        }
        // ---- barrier 1: u ready ----
        {
            __threadfence();
            __syncthreads();
            barNum++;
            if (tid == 0) {
                if (atomicAdd(&g_cnt, 1) == (unsigned)(gridDim.x - 1)) {
                    g_cnt = 0;
                    __threadfence();
                    atomicExch(&g_gen, barBase + barNum);
                } else {
                    while (*(volatile unsigned*)&g_gen != barBase + barNum) __nanosleep(32);
                }
            }
            __syncthreads();
        }
        // ================= phase B: G2 = u @ Geff^T + bias =================
        {
            float acc0 = 0.f, acc1 = 0.f, acc2 = 0.f, acc3 = 0.f;
            const float4* w4  = (const float4*)(sW + cB * 604);
            const float4* up0 = (const float4*)(u + (bgB * 4 + 0) * 600);
            const float4* up1 = (const float4*)(u + (bgB * 4 + 1) * 600);
            const float4* up2 = (const float4*)(u + (bgB * 4 + 2) * 600);
            const float4* up3 = (const float4*)(u + (bgB * 4 + 3) * 600);
#pragma unroll 5
            for (int k4 = 0; k4 < 150; k4++) {
                float4 w  = w4[k4];
                float4 a0 = __ldcg(up0 + k4);
                float4 a1 = __ldcg(up1 + k4);
                float4 a2 = __ldcg(up2 + k4);
                float4 a3 = __ldcg(up3 + k4);
                acc0 += w.x * a0.x + w.y * a0.y + w.z * a0.z + w.w * a0.w;
                acc1 += w.x * a1.x + w.y * a1.y + w.z * a1.z + w.w * a1.w;
                acc2 += w.x * a2.x + w.y * a2.y + w.z * a2.z + w.w * a2.w;
                acc3 += w.x * a3.x + w.y * a3.y + w.z * a3.z + w.w * a3.w;
            }
            if (nB < GEFFN) {
                G2[(bgB * 4 + 0) * GEFFN + nB] = acc0 + biasv;
                G2[(bgB * 4 + 1) * GEFFN + nB] = acc1 + biasv;
                G2[(bgB * 4 + 2) * GEFFN + nB] = acc2 + biasv;
                G2[(bgB * 4 + 3) * GEFFN + nB] = acc3 + biasv;
            }
        }
        // ---- barrier 2: G2 ready ----
        {
            __threadfence();
            __syncthreads();
            barNum++;
            if (tid == 0) {
                if (atomicAdd(&g_cnt, 1) == (unsigned)(gridDim.x - 1)) {
                    g_cnt = 0;
                    __threadfence();
                    atomicExch(&g_gen, barBase + barNum);
                } else {
                    while (*(volatile unsigned*)&g_gen != barBase + barNum) __nanosleep(32);
                }
            }
            __syncthreads();
        }
    }

    // ---- final GRU update: row 63 ----
    if (cta < 64) {
        int row = 63;
        const float* Gp = G2 + b * GEFFN;
        const float* xi = XI + (b * NSEQ + row) * G3;
        const float* xp = XP + (b * NSEQ + row) * G3;
        const float* q  = Hin + (b * NSEQ + row) * HID;
        float* h1r = H1 + (b * NSEQ + row) * HID;
        for (int d = tid; d < HID; d += 256) {
            float Md = __ldcg(Gp + 1800 + d);
            float r  = sigf(xi[d]       + __ldcg(Gp + d));
            float z  = sigf(xi[300 + d] + __ldcg(Gp + 300 + d));
            float nn = tanhf(xi[600 + d] + r * __ldcg(Gp + 600 + d));
            float Cc = (1.f - z) * nn + z * Md;
            float r2 = sigf(__ldcg(Gp + 900 + d)  + xp[d]);
            float z2 = sigf(__ldcg(Gp + 1200 + d) + xp[300 + d]);
            float n2 = tanhf(__ldcg(Gp + 1500 + d) + r2 * xp[600 + d]);
            float Pp = (1.f - z2) * n2 + z2 * q[d];
            h1r[d] = Cc + Pp;
        }
    }
}

// ---------------- Hcat = [H0..H4, features] ----------------
__global__ void k_concat(const float* __restrict__ feat) {
    int r = blockIdx.x;  // 0..4095
    for (int c = threadIdx.x; c < KCAT; c += blockDim.x) {
        float v;
        if (c < 1500) {
            int seg = c / 300, off = c - seg * 300;
            v = g_H[seg * HSZ + r * HID + off];
        } else {
            v = feat[r * EMB + (c - 1500)];
        }
        g_Hcat[r * KCAT + c] = v;
    }
}

extern "C" void kernel_launch(void* const* d_in, const int* in_sizes, int n_in,
                              void* d_out, int out_size) {
    const float* features = (const float*)d_in[0];
    const int*   speakers = (const int*)d_in[1];
    const float* w_in   = (const float*)d_in[2];
    const float* b_in   = (const float*)d_in[3];
    const float* gat_wq = (const float*)d_in[4];
    const float* gat_wk = (const float*)d_in[5];
    const float* gat_b  = (const float*)d_in[6];
    const float* wr0    = (const float*)d_in[7];
    const float* wr1    = (const float*)d_in[8];
    const float* wih_c  = (const float*)d_in[9];
    const float* whh_c  = (const float*)d_in[10];
    const float* bih_c  = (const float*)d_in[11];
    const float* bhh_c  = (const float*)d_in[12];
    const float* wih_p  = (const float*)d_in[13];
    const float* whh_p  = (const float*)d_in[14];
    const float* bih_p  = (const float*)d_in[15];
    const float* bhh_p  = (const float*)d_in[16];
    const float* w1 = (const float*)d_in[17];
    const float* b1 = (const float*)d_in[18];
    const float* w2 = (const float*)d_in[19];
    const float* b2 = (const float*)d_in[20];
    const float* w3 = (const float*)d_in[21];
    const float* b3 = (const float*)d_in[22];

    float *H, *XIp, *XPp, *Wr2Tp, *WGp, *Geffp, *up, *G2p, *Hcatp, *h1p, *h2p;
    int *startp;
    cudaGetSymbolAddress((void**)&H,     g_H);
    cudaGetSymbolAddress((void**)&XIp,   g_XI);
    cudaGetSymbolAddress((void**)&XPp,   g_XP);
    cudaGetSymbolAddress((void**)&Wr2Tp, g_Wr2T);
    cudaGetSymbolAddress((void**)&WGp,   g_WG);
    cudaGetSymbolAddress((void**)&Geffp, g_Geff);
    cudaGetSymbolAddress((void**)&up,    g_u);
    cudaGetSymbolAddress((void**)&G2p,   g_G2);
    cudaGetSymbolAddress((void**)&startp,g_start);
    cudaGetSymbolAddress((void**)&Hcatp, g_Hcat);
    cudaGetSymbolAddress((void**)&h1p,   g_h1);
    cudaGetSymbolAddress((void**)&h2p,   g_h2);

    const int MROWS = BATCH * NSEQ;   // 4096

    k_start<<<BATCH, NSEQ>>>(speakers, startp);

    // H0 = relu(features @ w_in.T + b_in)
    gemm_nt<<<dim3((HID + 63) / 64, MROWS / 64), 256>>>(
        features, w_in, b_in, H, MROWS, HID, EMB, 1);

    for (int l = 0; l < 4; l++) {
        const float* Hin = H + l * HSZ;
        float* H1 = H + (l + 1) * HSZ;
        const float* wih_c_l = wih_c + l * G3 * HID;
        const float* whh_c_l = whh_c + l * G3 * HID;
        const float* wih_p_l = wih_p + l * G3 * HID;
        const float* whh_p_l = whh_p + l * G3 * HID;
        const float* bih_c_l = bih_c + l * G3;
        const float* bhh_c_l = bhh_c + l * G3;
        const float* bih_p_l = bih_p + l * G3;
        const float* bhh_p_l = bhh_p + l * G3;
        const float* wq_l = gat_wq + l * HID;
        const float* wk_l = gat_wk + l * HID;

        // XI = Hin @ wih_c.T + bih_c ;  XP = Hin @ whh_p.T + bhh_p
        gemm_nt<<<dim3((G3 + 63) / 64, MROWS / 64), 256>>>(
            Hin, wih_c_l, bih_c_l, XIp, MROWS, G3, HID, 0);
        gemm_nt<<<dim3((G3 + 63) / 64, MROWS / 64), 256>>>(
            Hin, whh_p_l, bhh_p_l, XPp, MROWS, G3, HID, 0);

        // Geff: bottom rows (Wr2) + Wr2T
        k_wr2<<<(300 * 600 + 255) / 256, 256>>>(wr0 + l * HID * HID, wr1 + l * HID * HID);
        // WG = [whh_c ; wih_p]
        k_wg<<<(1800 * 300 + 255) / 256, 256>>>(whh_c_l, wih_p_l);
        // Geff top rows = WG @ Wr2  (via gemm_nt with Wr2T)
        gemm_nt<<<dim3((600 + 63) / 64, (1800 + 63) / 64), 256>>>(
            WGp, Wr2Tp, (const float*)nullptr, Geffp, 1800, 600, 300, 0);

        // whole sequential scan for this layer in one persistent kernel
        persist_layer<<<NCTA, 256>>>(
            Hin, H1, XIp, XPp, wq_l, wk_l, gat_b, l,
            speakers, startp, bhh_c_l, bih_p_l, Geffp, up, G2p);
    }

    k_concat<<<MROWS, 256>>>(features);

    gemm_nt<<<dim3((HID + 63) / 64, MROWS / 64), 256>>>(
        Hcatp, w1, b1, h1p, MROWS, HID, KCAT, 1);
    gemm_nt<<<dim3((HID + 63) / 64, MROWS / 64), 256>>>(
        h1p, w2, b2, h2p, MROWS, HID, HID, 1);
    gemm_nt<<<dim3(1, MROWS / 64), 256>>>(
        h2p, w3, b3, (float*)d_out, MROWS, 7, HID, 0);
}

// round 7
// speedup vs baseline: 1.3038x; 1.0583x over previous
#include <cuda_runtime.h>
#include <math.h>

#define HID   300
#define G3    900
#define NSEQ  64
#define BATCH 64
#define EMB   1024
#define KCAT  2524
#define HSZ   (BATCH*NSEQ*HID)
#define NCTA  132
#define GEFFN 2100

__device__ float g_H[5 * HSZ];
__device__ float g_XI[BATCH * NSEQ * G3];
__device__ float g_XP[BATCH * NSEQ * G3];
__device__ float g_Wr2T[600 * HID];
__device__ float g_WG[1800 * HID];
__device__ float g_Geff[GEFFN * 600];
__device__ float g_u[BATCH * 600];
__device__ float g_G2[BATCH * GEFFN];
__device__ int   g_start[BATCH * NSEQ];
__device__ float g_Hcat[BATCH * NSEQ * KCAT];
__device__ float g_h1[BATCH * NSEQ * HID];
__device__ float g_h2[BATCH * NSEQ * HID];

__device__ volatile unsigned g_cnt;
__device__ volatile unsigned g_gen;

__global__ void k_reset() { g_cnt = 0; g_gen = 0; }

__device__ __forceinline__ float sigf(float x) { return 1.0f / (1.0f + expf(-x)); }

__device__ __forceinline__ float blockReduceSum(float v, float* s) {
    int tid = threadIdx.x;
    s[tid] = v; __syncthreads();
    for (int o = 128; o > 0; o >>= 1) { if (tid < o) s[tid] += s[tid + o]; __syncthreads(); }
    float r = s[0]; __syncthreads(); return r;
}
__device__ __forceinline__ float blockReduceMax(float v, float* s) {
    int tid = threadIdx.x;
    s[tid] = v; __syncthreads();
    for (int o = 128; o > 0; o >>= 1) { if (tid < o) s[tid] = fmaxf(s[tid], s[tid + o]); __syncthreads(); }
    float r = s[0]; __syncthreads(); return r;
}

// grid barrier: fire-and-forget arrival + monotonic generation release
__device__ __forceinline__ void gbar(unsigned bar, int tid, int cta) {
    __syncthreads();
    if (tid == 0) {
        __threadfence();
        asm volatile("red.global.add.u32 [%0], %1;" :: "l"((const void*)&g_cnt), "r"(1u) : "memory");
        if (cta == 0) {
            while (g_cnt < NCTA * bar) __nanosleep(20);
            __threadfence();
            g_gen = bar;
        } else {
            while (g_gen < bar) __nanosleep(20);
        }
        asm volatile("fence.acq_rel.gpu;" ::: "memory");
    }
    __syncthreads();
}

__global__ void k_start(const int* __restrict__ spk, int* __restrict__ start) {
    int b = blockIdx.x, i = threadIdx.x;
    int s = spk[b * NSEQ + i];
    int last = -1;
    for (int j = 0; j < i; j++)
        if (spk[b * NSEQ + j] == s) last = j;
    start[b * NSEQ + i] = last > 0 ? last : 0;
}

// ---- dense GEMM: C=A@B^T+bias (opt relu). BM=128,BN=64,BK=16, 8x4 micro ----
__global__ void __launch_bounds__(256) gemm128(
    const float* __restrict__ A, const float* __restrict__ B,
    const float* __restrict__ bias, float* __restrict__ C,
    int M, int N, int K, int relu)
{
    __shared__ float sA[16 * 132];
    __shared__ float sB[16 * 68];
    int tid = threadIdx.x;
    int m0 = blockIdx.y * 128, n0 = blockIdx.x * 64;
    int tm = tid & 15, tn = tid >> 4;
    int lr = tid >> 2, lk = (tid & 3) * 4;
    float acc[8][4];
#pragma unroll
    for (int i = 0; i < 8; i++)
#pragma unroll
        for (int j = 0; j < 4; j++) acc[i][j] = 0.f;

    for (int k0 = 0; k0 < K; k0 += 16) {
#pragma unroll
        for (int h = 0; h < 2; h++) {
            int m = lr + h * 64, gm = m0 + m, kb = k0 + lk;
            float4 av = make_float4(0.f, 0.f, 0.f, 0.f);
            if (gm < M) {
                if (kb + 3 < K) av = *(const float4*)(A + (size_t)gm * K + kb);
                else {
                    if (kb     < K) av.x = A[(size_t)gm * K + kb];
                    if (kb + 1 < K) av.y = A[(size_t)gm * K + kb + 1];
                    if (kb + 2 < K) av.z = A[(size_t)gm * K + kb + 2];
                }
            }
            sA[(lk + 0) * 132 + m] = av.x;
            sA[(lk + 1) * 132 + m] = av.y;
            sA[(lk + 2) * 132 + m] = av.z;
            sA[(lk + 3) * 132 + m] = av.w;
        }
        {
            int gn = n0 + lr, kb = k0 + lk;
            float4 bv = make_float4(0.f, 0.f, 0.f, 0.f);
            if (gn < N) {
                if (kb + 3 < K) bv = *(const float4*)(B + (size_t)gn * K + kb);
                else {
                    if (kb     < K) bv.x = B[(size_t)gn * K + kb];
                    if (kb + 1 < K) bv.y = B[(size_t)gn * K + kb + 1];
                    if (kb + 2 < K) bv.z = B[(size_t)gn * K + kb + 2];
                }
            }
            sB[(lk + 0) * 68 + lr] = bv.x;
            sB[(lk + 1) * 68 + lr] = bv.y;
            sB[(lk + 2) * 68 + lr] = bv.z;
            sB[(lk + 3) * 68 + lr] = bv.w;
        }
        __syncthreads();
#pragma unroll
        for (int kk = 0; kk < 16; kk++) {
            float4 x0 = *(const float4*)(sA + kk * 132 + tm * 4);
            float4 x1 = *(const float4*)(sA + kk * 132 + 64 + tm * 4);
            float4 y0 = *(const float4*)(sB + kk * 68 + tn * 4);
            float a[8] = {x0.x, x0.y, x0.z, x0.w, x1.x, x1.y, x1.z, x1.w};
            float bv[4] = {y0.x, y0.y, y0.z, y0.w};
#pragma unroll
            for (int i = 0; i < 8; i++)
#pragma unroll
                for (int j = 0; j < 4; j++) acc[i][j] += a[i] * bv[j];
        }
        __syncthreads();
    }
#pragma unroll
    for (int i = 0; i < 8; i++) {
        int m = m0 + ((i < 4) ? (tm * 4 + i) : (64 + tm * 4 + i - 4));
        if (m >= M) continue;
#pragma unroll
        for (int j = 0; j < 4; j++) {
            int n = n0 + tn * 4 + j;
            if (n >= N) continue;
            float v = acc[i][j] + (bias ? bias[n] : 0.f);
            if (relu) v = fmaxf(v, 0.f);
            C[(size_t)m * N + n] = v;
        }
    }
}

__global__ void k_wr2(const float* __restrict__ wr0, const float* __restrict__ wr1) {
    int idx = blockIdx.x * blockDim.x + threadIdx.x;
    if (idx < 300 * 600) {
        int d = idx / 600, e = idx - d * 600;
        float v = (e < 300) ? wr0[d * 300 + e] : wr1[d * 300 + (e - 300)];
        g_Wr2T[e * 300 + d] = v;
        g_Geff[(1800 + d) * 600 + e] = v;
    }
}

__global__ void k_wg(const float* __restrict__ whh_c, const float* __restrict__ wih_p) {
    int idx = blockIdx.x * blockDim.x + threadIdx.x;
    if (idx < 1800 * 300) {
        int n = idx / 300, d = idx - n * 300;
        g_WG[idx] = (n < 900) ? whh_c[n * 300 + d] : wih_p[(n - 900) * 300 + d];
    }
}

// ---------------- persistent per-layer scan kernel ----------------
__global__ void __launch_bounds__(256, 1) persist_layer(
    const float* __restrict__ Hin, float* __restrict__ H1,
    const float* __restrict__ XI, const float* __restrict__ XP,
    const float* __restrict__ wq, const float* __restrict__ wk,
    const float* __restrict__ gatb, int layer,
    const int* __restrict__ spk, const int* __restrict__ start,
    const float* __restrict__ bhh_c, const float* __restrict__ bih_p,
    const float* __restrict__ Geff, float* __restrict__ u,
    float* __restrict__ G2)
{
    __shared__ float sW[16 * 604];
    __shared__ float s_red[256];
    __shared__ float s_w[64];
    __shared__ float s_sm[64];
    __shared__ float s_kdot[64];

    const int tid = threadIdx.x;
    const int cta = blockIdx.x;
    const int b = cta;
    const int n0 = cta * 16;

    for (int idx = tid; idx < 16 * 600; idx += 256) {
        int c = idx / 600, k = idx - c * 600;
        int n = n0 + c;
        sW[c * 604 + k] = (n < GEFFN) ? Geff[n * 600 + k] : 0.f;
    }

    const int cB = tid & 15, bgB = tid >> 4;
    const int nB = n0 + cB;
    float biasv = 0.f;
    if (nB < 900) biasv = bhh_c[nB];
    else if (nB < 1800) biasv = bih_p[nB - 900];

    unsigned bar = 0;
    const float gb = gatb[layer];

    if (cta < 64) {
        const float* xi = XI + b * NSEQ * G3;
        const float* xp = XP + b * NSEQ * G3;
        const float* x0 = Hin + b * NSEQ * HID;
        float* h1 = H1 + b * NSEQ * HID;
        float kp = 0.f;
        for (int d = tid; d < HID; d += 256) {
            float r  = sigf(xi[d] + bhh_c[d]);
            float z  = sigf(xi[300 + d] + bhh_c[300 + d]);
            float nn = tanhf(xi[600 + d] + r * bhh_c[600 + d]);
            float C0 = (1.f - z) * nn;
            float r2 = sigf(bih_p[d] + xp[d]);
            float z2 = sigf(bih_p[300 + d] + xp[300 + d]);
            float n2 = tanhf(bih_p[600 + d] + r2 * xp[600 + d]);
            float P0 = (1.f - z2) * n2 + z2 * x0[d];
            float h = C0 + P0;
            h1[d] = h;
            kp += h * wk[d];
        }
        float ks = blockReduceSum(kp, s_red);
        if (tid == 0) s_kdot[0] = ks;
    }
    __syncthreads();

    for (int i = 1; i <= 63; i++) {
        // ===== phase A: GRU update row i-1, attention -> u(i) =====
        if (cta < 64) {
            if (i >= 2) {
                int row = i - 1;
                const float* Gp = G2 + b * GEFFN;
                const float* xi = XI + (b * NSEQ + row) * G3;
                const float* xp = XP + (b * NSEQ + row) * G3;
                const float* q  = Hin + (b * NSEQ + row) * HID;
                float* h1r = H1 + (b * NSEQ + row) * HID;
                float kp = 0.f;
                for (int d = tid; d < HID; d += 256) {
                    float Md = __ldcg(Gp + 1800 + d);
                    float r  = sigf(xi[d]       + __ldcg(Gp + d));
                    float z  = sigf(xi[300 + d] + __ldcg(Gp + 300 + d));
                    float nn = tanhf(xi[600 + d] + r * __ldcg(Gp + 600 + d));
                    float Cc = (1.f - z) * nn + z * Md;
                    float r2 = sigf(__ldcg(Gp + 900 + d)  + xp[d]);
                    float z2 = sigf(__ldcg(Gp + 1200 + d) + xp[300 + d]);
                    float n2 = tanhf(__ldcg(Gp + 1500 + d) + r2 * xp[600 + d]);
                    float Pp = (1.f - z2) * n2 + z2 * q[d];
                    float h = Cc + Pp;
                    h1r[d] = h;
                    kp += h * wk[d];
                }
                float ks = blockReduceSum(kp, s_red);
                if (tid == 0) s_kdot[row] = ks;
                __syncthreads();
            }
            const float* qrow = Hin + (b * NSEQ + i) * HID;
            float qp = 0.f;
            for (int d = tid; d < HID; d += 256) qp += qrow[d] * wq[d];
            float qd = blockReduceSum(qp, s_red);

            int st = start[b * NSEQ + i];
            int cnt = i - st;
            int spki = spk[b * NSEQ + i];

            float aj = -1e30f;
            if (tid < cnt) aj = qd + s_kdot[st + tid] + gb;
            float mx = blockReduceMax(aj, s_red);
            float e = (tid < cnt) ? expf(aj - mx) : 0.f;
            float se = blockReduceSum(e, s_red);
            if (tid < cnt) {
                s_w[tid]  = e / se;
                s_sm[tid] = (spk[b * NSEQ + st + tid] == spki) ? 1.f : 0.f;
            }
            __syncthreads();
            for (int d = tid; d < 600; d += 256) {
                int ei = (d < 300) ? d : d - 300;
                float u0f = (d < 300) ? 1.f : 0.f;
                const float* base = H1 + (b * NSEQ + st) * HID + ei;
                float acc = 0.f;
                for (int j = 0; j < cnt; j++) {
                    float m = s_sm[j];
                    float sel = u0f * m + (1.f - u0f) * (1.f - m);
                    acc += s_w[j] * sel * base[j * HID];
                }
                u[b * 600 + d] = acc;
            }
        }
        gbar(++bar, tid, cta);   // u ready

        // ===== phase B: G2 = u @ Geff^T + bias =====
        {
            float acc0 = 0.f, acc1 = 0.f, acc2 = 0.f, acc3 = 0.f;
            const float4* w4  = (const float4*)(sW + cB * 604);
            const float4* up0 = (const float4*)(u + (bgB * 4 + 0) * 600);
            const float4* up1 = (const float4*)(u + (bgB * 4 + 1) * 600);
            const float4* up2 = (const float4*)(u + (bgB * 4 + 2) * 600);
            const float4* up3 = (const float4*)(u + (bgB * 4 + 3) * 600);
#pragma unroll 10
            for (int k4 = 0; k4 < 150; k4++) {
                float4 w  = w4[k4];
                float4 a0 = __ldcg(up0 + k4);
                float4 a1 = __ldcg(up1 + k4);
                float4 a2 = __ldcg(up2 + k4);
                float4 a3 = __ldcg(up3 + k4);
                acc0 += w.x * a0.x + w.y * a0.y + w.z * a0.z + w.w * a0.w;
                acc1 += w.x * a1.x + w.y * a1.y + w.z * a1.z + w.w * a1.w;
                acc2 += w.x * a2.x + w.y * a2.y + w.z * a2.z + w.w * a2.w;
                acc3 += w.x * a3.x + w.y * a3.y + w.z * a3.z + w.w * a3.w;
            }
            if (nB < GEFFN) {
                G2[(bgB * 4 + 0) * GEFFN + nB] = acc0 + biasv;
                G2[(bgB * 4 + 1) * GEFFN + nB] = acc1 + biasv;
                G2[(bgB * 4 + 2) * GEFFN + nB] = acc2 + biasv;
                G2[(bgB * 4 + 3) * GEFFN + nB] = acc3 + biasv;
            }
        }
        gbar(++bar, tid, cta);   // G2 ready
    }

    // final GRU update: row 63
    if (cta < 64) {
        int row = 63;
        const float* Gp = G2 + b * GEFFN;
        const float* xi = XI + (b * NSEQ + row) * G3;
        const float* xp = XP + (b * NSEQ + row) * G3;
        const float* q  = Hin + (b * NSEQ + row) * HID;
        float* h1r = H1 + (b * NSEQ + row) * HID;
        for (int d = tid; d < HID; d += 256) {
            float Md = __ldcg(Gp + 1800 + d);
            float r  = sigf(xi[d]       + __ldcg(Gp + d));
            float z  = sigf(xi[300 + d] + __ldcg(Gp + 300 + d));
            float nn = tanhf(xi[600 + d] + r * __ldcg(Gp + 600 + d));
            float Cc = (1.f - z) * nn + z * Md;
            float r2 = sigf(__ldcg(Gp + 900 + d)  + xp[d]);
            float z2 = sigf(__ldcg(Gp + 1200 + d) + xp[300 + d]);
            float n2 = tanhf(__ldcg(Gp + 1500 + d) + r2 * xp[600 + d]);
            float Pp = (1.f - z2) * n2 + z2 * q[d];
            h1r[d] = Cc + Pp;
        }
    }
}

__global__ void k_concat(const float* __restrict__ feat) {
    int r = blockIdx.x;
    for (int c = threadIdx.x; c < KCAT; c += blockDim.x) {
        float v;
        if (c < 1500) {
            int seg = c / 300, off = c - seg * 300;
            v = g_H[seg * HSZ + r * HID + off];
        } else {
            v = feat[r * EMB + (c - 1500)];
        }
        g_Hcat[r * KCAT + c] = v;
    }
}

extern "C" void kernel_launch(void* const* d_in, const int* in_sizes, int n_in,
                              void* d_out, int out_size) {
    const float* features = (const float*)d_in[0];
    const int*   speakers = (const int*)d_in[1];
    const float* w_in   = (const float*)d_in[2];
    const float* b_in   = (const float*)d_in[3];
    const float* gat_wq = (const float*)d_in[4];
    const float* gat_wk = (const float*)d_in[5];
    const float* gat_b  = (const float*)d_in[6];
    const float* wr0    = (const float*)d_in[7];
    const float* wr1    = (const float*)d_in[8];
    const float* wih_c  = (const float*)d_in[9];
    const float* whh_c  = (const float*)d_in[10];
    const float* bih_c  = (const float*)d_in[11];
    const float* bhh_c  = (const float*)d_in[12];
    const float* wih_p  = (const float*)d_in[13];
    const float* whh_p  = (const float*)d_in[14];
    const float* bih_p  = (const float*)d_in[15];
    const float* bhh_p  = (const float*)d_in[16];
    const float* w1 = (const float*)d_in[17];
    const float* b1 = (const float*)d_in[18];
    const float* w2 = (const float*)d_in[19];
    const float* b2 = (const float*)d_in[20];
    const float* w3 = (const float*)d_in[21];
    const float* b3 = (const float*)d_in[22];

    float *H, *XIp, *XPp, *Wr2Tp, *WGp, *Geffp, *up, *G2p, *Hcatp, *h1p, *h2p;
    int *startp;
    cudaGetSymbolAddress((void**)&H,     g_H);
    cudaGetSymbolAddress((void**)&XIp,   g_XI);
    cudaGetSymbolAddress((void**)&XPp,   g_XP);
    cudaGetSymbolAddress((void**)&Wr2Tp, g_Wr2T);
    cudaGetSymbolAddress((void**)&WGp,   g_WG);
    cudaGetSymbolAddress((void**)&Geffp, g_Geff);
    cudaGetSymbolAddress((void**)&up,    g_u);
    cudaGetSymbolAddress((void**)&G2p,   g_G2);
    cudaGetSymbolAddress((void**)&startp,g_start);
    cudaGetSymbolAddress((void**)&Hcatp, g_Hcat);
    cudaGetSymbolAddress((void**)&h1p,   g_h1);
    cudaGetSymbolAddress((void**)&h2p,   g_h2);

    const int MROWS = BATCH * NSEQ;

    k_start<<<BATCH, NSEQ>>>(speakers, startp);

    gemm128<<<dim3((HID + 63) / 64, MROWS / 128), 256>>>(
        features, w_in, b_in, H, MROWS, HID, EMB, 1);

    for (int l = 0; l < 4; l++) {
        const float* Hin = H + l * HSZ;
        float* H1 = H + (l + 1) * HSZ;
        const float* wih_c_l = wih_c + l * G3 * HID;
        const float* whh_c_l = whh_c + l * G3 * HID;
        const float* wih_p_l = wih_p + l * G3 * HID;
        const float* whh_p_l = whh_p + l * G3 * HID;
        const float* bhh_c_l = bhh_c + l * G3;
        const float* bih_c_l = bih_c + l * G3;
        const float* bih_p_l = bih_p + l * G3;
        const float* bhh_p_l = bhh_p + l * G3;
        const float* wq_l = gat_wq + l * HID;
        const float* wk_l = gat_wk + l * HID;

        gemm128<<<dim3((G3 + 63) / 64, MROWS / 128), 256>>>(
            Hin, wih_c_l, bih_c_l, XIp, MROWS, G3, HID, 0);
        gemm128<<<dim3((G3 + 63) / 64, MROWS / 128), 256>>>(
            Hin, whh_p_l, bhh_p_l, XPp, MROWS, G3, HID, 0);

        k_wr2<<<(300 * 600 + 255) / 256, 256>>>(wr0 + l * HID * HID, wr1 + l * HID * HID);
        k_wg<<<(1800 * 300 + 255) / 256, 256>>>(whh_c_l, wih_p_l);
        gemm128<<<dim3((600 + 63) / 64, (1800 + 127) / 128), 256>>>(
            WGp, Wr2Tp, (const float*)nullptr, Geffp, 1800, 600, 300, 0);

        k_reset<<<1, 1>>>();
        persist_layer<<<NCTA, 256>>>(
            Hin, H1, XIp, XPp, wq_l, wk_l, gat_b, l,
            speakers, startp, bhh_c_l, bih_p_l, Geffp, up, G2p);
    }

    k_concat<<<MROWS, 256>>>(features);

    gemm128<<<dim3((HID + 63) / 64, MROWS / 128), 256>>>(
        Hcatp, w1, b1, h1p, MROWS, HID, KCAT, 1);
    gemm128<<<dim3((HID + 63) / 64, MROWS / 128), 256>>>(
        h1p, w2, b2, h2p, MROWS, HID, HID, 1);
    gemm128<<<dim3(1, MROWS / 128), 256>>>(
        h2p, w3, b3, (float*)d_out, MROWS, 7, HID, 0);
}

// round 8
// speedup vs baseline: 1.5122x; 1.1599x over previous
#include <cuda_runtime.h>
#include <math.h>

#define HID   300
#define G3    900
#define NSEQ  64
#define BATCH 64
#define EMB   1024
#define KCAT  2524
#define HSZ   (BATCH*NSEQ*HID)
#define NCTA  132
#define GEFFN 2100
#define DSMEM_FLOATS (16*604 + 600*64)

__device__ float g_H[5 * HSZ];
__device__ float g_XI[BATCH * NSEQ * G3];
__device__ float g_XP[BATCH * NSEQ * G3];
__device__ float g_Wr2T[600 * HID];
__device__ float g_WG[1800 * HID];
__device__ float g_Geff[GEFFN * 600];
__device__ float g_uT[600 * BATCH];            // transposed: uT[d*64 + b]
__device__ float g_G2[BATCH * GEFFN];
__device__ int   g_start[BATCH * NSEQ];
__device__ float g_Hcat[BATCH * NSEQ * KCAT];
__device__ float g_h1[BATCH * NSEQ * HID];
__device__ float g_h2[BATCH * NSEQ * HID];

__device__ volatile unsigned g_cnt;
__device__ volatile unsigned g_gen;

__global__ void k_reset() { g_cnt = 0; g_gen = 0; }

__device__ __forceinline__ float sigf(float x) { return 1.0f / (1.0f + expf(-x)); }

// 256-thread reductions: shuffle + 8-slot smem, 3 syncthreads
__device__ __forceinline__ float bsum(float v, float* s8) {
    int tid = threadIdx.x;
#pragma unroll
    for (int o = 16; o > 0; o >>= 1) v += __shfl_xor_sync(0xffffffffu, v, o);
    if ((tid & 31) == 0) s8[tid >> 5] = v;
    __syncthreads();
    if (tid < 32) {
        float t = (tid < 8) ? s8[tid] : 0.f;
#pragma unroll
        for (int o = 4; o > 0; o >>= 1) t += __shfl_xor_sync(0xffffffffu, t, o);
        if (tid == 0) s8[0] = t;
    }
    __syncthreads();
    float r = s8[0];
    __syncthreads();
    return r;
}
__device__ __forceinline__ float bmax(float v, float* s8) {
    int tid = threadIdx.x;
#pragma unroll
    for (int o = 16; o > 0; o >>= 1) v = fmaxf(v, __shfl_xor_sync(0xffffffffu, v, o));
    if ((tid & 31) == 0) s8[tid >> 5] = v;
    __syncthreads();
    if (tid < 32) {
        float t = (tid < 8) ? s8[tid] : -1e30f;
#pragma unroll
        for (int o = 4; o > 0; o >>= 1) t = fmaxf(t, __shfl_xor_sync(0xffffffffu, t, o));
        if (tid == 0) s8[0] = t;
    }
    __syncthreads();
    float r = s8[0];
    __syncthreads();
    return r;
}

// grid barrier: fire-and-forget arrival + monotonic generation release
__device__ __forceinline__ void gbar(unsigned bar, int tid, int cta) {
    __syncthreads();
    if (tid == 0) {
        __threadfence();
        asm volatile("red.global.add.u32 [%0], %1;" :: "l"((const void*)&g_cnt), "r"(1u) : "memory");
        if (cta == 0) {
            while (g_cnt < NCTA * bar) __nanosleep(20);
            __threadfence();
            g_gen = bar;
        } else {
            while (g_gen < bar) __nanosleep(20);
        }
        asm volatile("fence.acq_rel.gpu;" ::: "memory");
    }
    __syncthreads();
}

__global__ void k_start(const int* __restrict__ spk, int* __restrict__ start) {
    int b = blockIdx.x, i = threadIdx.x;
    int s = spk[b * NSEQ + i];
    int last = -1;
    for (int j = 0; j < i; j++)
        if (spk[b * NSEQ + j] == s) last = j;
    start[b * NSEQ + i] = last > 0 ? last : 0;
}

// ---- dense GEMM: C=A@B^T+bias (opt relu). BM=128,BN=64,BK=16, 8x4 micro ----
__global__ void __launch_bounds__(256) gemm128(
    const float* __restrict__ A, const float* __restrict__ B,
    const float* __restrict__ bias, float* __restrict__ C,
    int M, int N, int K, int relu)
{
    __shared__ float sA[16 * 132];
    __shared__ float sB[16 * 68];
    int tid = threadIdx.x;
    int m0 = blockIdx.y * 128, n0 = blockIdx.x * 64;
    int tm = tid & 15, tn = tid >> 4;
    int lr = tid >> 2, lk = (tid & 3) * 4;
    float acc[8][4];
#pragma unroll
    for (int i = 0; i < 8; i++)
#pragma unroll
        for (int j = 0; j < 4; j++) acc[i][j] = 0.f;

    for (int k0 = 0; k0 < K; k0 += 16) {
#pragma unroll
        for (int h = 0; h < 2; h++) {
            int m = lr + h * 64, gm = m0 + m, kb = k0 + lk;
            float4 av = make_float4(0.f, 0.f, 0.f, 0.f);
            if (gm < M) {
                if (kb + 3 < K) av = *(const float4*)(A + (size_t)gm * K + kb);
                else {
                    if (kb     < K) av.x = A[(size_t)gm * K + kb];
                    if (kb + 1 < K) av.y = A[(size_t)gm * K + kb + 1];
                    if (kb + 2 < K) av.z = A[(size_t)gm * K + kb + 2];
                }
            }
            sA[(lk + 0) * 132 + m] = av.x;
            sA[(lk + 1) * 132 + m] = av.y;
            sA[(lk + 2) * 132 + m] = av.z;
            sA[(lk + 3) * 132 + m] = av.w;
        }
        {
            int gn = n0 + lr, kb = k0 + lk;
            float4 bv = make_float4(0.f, 0.f, 0.f, 0.f);
            if (gn < N) {
                if (kb + 3 < K) bv = *(const float4*)(B + (size_t)gn * K + kb);
                else {
                    if (kb     < K) bv.x = B[(size_t)gn * K + kb];
                    if (kb + 1 < K) bv.y = B[(size_t)gn * K + kb + 1];
                    if (kb + 2 < K) bv.z = B[(size_t)gn * K + kb + 2];
                }
            }
            sB[(lk + 0) * 68 + lr] = bv.x;
            sB[(lk + 1) * 68 + lr] = bv.y;
            sB[(lk + 2) * 68 + lr] = bv.z;
            sB[(lk + 3) * 68 + lr] = bv.w;
        }
        __syncthreads();
#pragma unroll
        for (int kk = 0; kk < 16; kk++) {
            float4 x0 = *(const float4*)(sA + kk * 132 + tm * 4);
            float4 x1 = *(const float4*)(sA + kk * 132 + 64 + tm * 4);
            float4 y0 = *(const float4*)(sB + kk * 68 + tn * 4);
            float a[8] = {x0.x, x0.y, x0.z, x0.w, x1.x, x1.y, x1.z, x1.w};
            float bv[4] = {y0.x, y0.y, y0.z, y0.w};
#pragma unroll
            for (int i = 0; i < 8; i++)
#pragma unroll
                for (int j = 0; j < 4; j++) acc[i][j] += a[i] * bv[j];
        }
        __syncthreads();
    }
#pragma unroll
    for (int i = 0; i < 8; i++) {
        int m = m0 + ((i < 4) ? (tm * 4 + i) : (64 + tm * 4 + i - 4));
        if (m >= M) continue;
#pragma unroll
        for (int j = 0; j < 4; j++) {
            int n = n0 + tn * 4 + j;
            if (n >= N) continue;
            float v = acc[i][j] + (bias ? bias[n] : 0.f);
            if (relu) v = fmaxf(v, 0.f);
            C[(size_t)m * N + n] = v;
        }
    }
}

__global__ void k_wr2(const float* __restrict__ wr0, const float* __restrict__ wr1) {
    int idx = blockIdx.x * blockDim.x + threadIdx.x;
    if (idx < 300 * 600) {
        int d = idx / 600, e = idx - d * 600;
        float v = (e < 300) ? wr0[d * 300 + e] : wr1[d * 300 + (e - 300)];
        g_Wr2T[e * 300 + d] = v;
        g_Geff[(1800 + d) * 600 + e] = v;
    }
}

__global__ void k_wg(const float* __restrict__ whh_c, const float* __restrict__ wih_p) {
    int idx = blockIdx.x * blockDim.x + threadIdx.x;
    if (idx < 1800 * 300) {
        int n = idx / 300, d = idx - n * 300;
        g_WG[idx] = (n < 900) ? whh_c[n * 300 + d] : wih_p[(n - 900) * 300 + d];
    }
}

// ---------------- persistent per-layer scan kernel ----------------
__global__ void __launch_bounds__(256, 1) persist_layer(
    const float* __restrict__ Hin, float* __restrict__ H1,
    const float* __restrict__ XI, const float* __restrict__ XP,
    const float* __restrict__ wq, const float* __restrict__ wk,
    const float* __restrict__ gatb, int layer,
    const int* __restrict__ spk, const int* __restrict__ start,
    const float* __restrict__ bhh_c, const float* __restrict__ bih_p,
    const float* __restrict__ Geff, float* __restrict__ uT,
    float* __restrict__ G2)
{
    extern __shared__ float dsm[];
    float* sW = dsm;                 // 16*604
    float* sU = dsm + 16 * 604;      // 600*64, layout [d*64 + b]

    __shared__ float s8[8];
    __shared__ float s_w0[64];
    __shared__ float s_w1[64];
    __shared__ float s_kdot[64];

    const int tid = threadIdx.x;
    const int cta = blockIdx.x;
    const int b = cta;
    const int n0 = cta * 16;

    for (int idx = tid; idx < 16 * 600; idx += 256) {
        int c = idx / 600, k = idx - c * 600;
        int n = n0 + c;
        sW[c * 604 + k] = (n < GEFFN) ? Geff[(size_t)n * 600 + k] : 0.f;
    }

    // phase-B mapping: col cB (0..15), batch group bpg (0..15) -> batches 4bpg..4bpg+3
    const int cB = tid & 15, bpg = tid >> 4;
    const int nB = n0 + cB;
    float biasv = 0.f;
    if (nB < 900) biasv = bhh_c[nB];
    else if (nB < 1800) biasv = bih_p[nB - 900];
    const float4* wrow = (const float4*)(sW + cB * 604);
    unsigned uAddr = (unsigned)__cvta_generic_to_shared(sU) + bpg * 16;

    unsigned bar = 0;
    const float gb = gatb[layer];

    if (cta < 64) {
        const float* xi = XI + (size_t)b * NSEQ * G3;
        const float* xp = XP + (size_t)b * NSEQ * G3;
        const float* x0 = Hin + (size_t)b * NSEQ * HID;
        float* h1 = H1 + (size_t)b * NSEQ * HID;
        float kp = 0.f;
        for (int d = tid; d < HID; d += 256) {
            float r  = sigf(xi[d] + bhh_c[d]);
            float z  = sigf(xi[300 + d] + bhh_c[300 + d]);
            float nn = tanhf(xi[600 + d] + r * bhh_c[600 + d]);
            float C0 = (1.f - z) * nn;
            float r2 = sigf(bih_p[d] + xp[d]);
            float z2 = sigf(bih_p[300 + d] + xp[300 + d]);
            float n2 = tanhf(bih_p[600 + d] + r2 * xp[600 + d]);
            float P0 = (1.f - z2) * n2 + z2 * x0[d];
            float h = C0 + P0;
            h1[d] = h;
            kp += h * wk[d];
        }
        float ks = bsum(kp, s8);
        if (tid == 0) s_kdot[0] = ks;
    }
    __syncthreads();

    for (int i = 1; i <= 63; i++) {
        // ===== phase A (CTAs 0..63): GRU row i-1, attention -> uT =====
        if (cta < 64) {
            if (i >= 2) {
                int row = i - 1;
                const float* Gp = G2 + (size_t)b * GEFFN;
                const float* xi = XI + ((size_t)b * NSEQ + row) * G3;
                const float* xp = XP + ((size_t)b * NSEQ + row) * G3;
                const float* q  = Hin + ((size_t)b * NSEQ + row) * HID;
                float* h1r = H1 + ((size_t)b * NSEQ + row) * HID;
                float kp = 0.f;
                for (int d = tid; d < HID; d += 256) {
                    float Md = __ldcg(Gp + 1800 + d);
                    float r  = sigf(xi[d]       + __ldcg(Gp + d));
                    float z  = sigf(xi[300 + d] + __ldcg(Gp + 300 + d));
                    float nn = tanhf(xi[600 + d] + r * __ldcg(Gp + 600 + d));
                    float Cc = (1.f - z) * nn + z * Md;
                    float r2 = sigf(__ldcg(Gp + 900 + d)  + xp[d]);
                    float z2 = sigf(__ldcg(Gp + 1200 + d) + xp[300 + d]);
                    float n2 = tanhf(__ldcg(Gp + 1500 + d) + r2 * xp[600 + d]);
                    float Pp = (1.f - z2) * n2 + z2 * q[d];
                    float h = Cc + Pp;
                    h1r[d] = h;
                    kp += h * wk[d];
                }
                float ks = bsum(kp, s8);
                if (tid == 0) s_kdot[row] = ks;
                __syncthreads();
            }
            const float* qrow = Hin + ((size_t)b * NSEQ + i) * HID;
            float qp = 0.f;
            for (int d = tid; d < HID; d += 256) qp += qrow[d] * wq[d];
            float qd = bsum(qp, s8);

            int st = start[b * NSEQ + i];
            int cnt = i - st;
            int spki = spk[b * NSEQ + i];

            float aj = -1e30f;
            if (tid < cnt) aj = qd + s_kdot[st + tid] + gb;
            float mx = bmax(aj, s8);
            float e = (tid < cnt) ? expf(aj - mx) : 0.f;
            float se = bsum(e, s8);
            if (tid < cnt) {
                float w = e / se;
                float smv = (spk[b * NSEQ + st + tid] == spki) ? 1.f : 0.f;
                s_w0[tid] = w * smv;
                s_w1[tid] = w * (1.f - smv);
            }
            __syncthreads();
            for (int d = tid; d < 600; d += 256) {
                int ei = (d < 300) ? d : d - 300;
                const float* wt = (d < 300) ? s_w0 : s_w1;
                const float* base = H1 + ((size_t)b * NSEQ + st) * HID + ei;
                float acc = 0.f;
                for (int j = 0; j < cnt; j++)
                    acc += wt[j] * base[j * HID];
                __stcg(uT + d * 64 + b, acc);
            }
        }
        gbar(++bar, tid, cta);   // u ready

        // ===== stage uT into SMEM (all CTAs) =====
        {
            const float4* src = (const float4*)uT;
            float4* dst = (float4*)sU;
            for (int idx = tid; idx < 9600; idx += 256)
                dst[idx] = __ldcg(src + idx);
        }
        __syncthreads();

        // ===== phase B: G2 = u @ Geff^T + bias (f32x2 packed) =====
        {
            unsigned long long a01 = 0ull, a23 = 0ull;
            for (int k4 = 0; k4 < 150; k4++) {
                float4 w = wrow[k4];
                unsigned base = uAddr + (unsigned)(k4 * 1024);
#define PB_STEP(OFF, WC) { \
                unsigned long long p01, p23, wp; \
                asm volatile("ld.shared.v2.u64 {%0,%1},[%2];" : "=l"(p01), "=l"(p23) : "r"(base + OFF)); \
                asm volatile("mov.b64 %0,{%1,%1};" : "=l"(wp) : "f"(WC)); \
                asm volatile("fma.rn.f32x2 %0,%1,%2,%0;" : "+l"(a01) : "l"(p01), "l"(wp)); \
                asm volatile("fma.rn.f32x2 %0,%1,%2,%0;" : "+l"(a23) : "l"(p23), "l"(wp)); }
                PB_STEP(0u,   w.x)
                PB_STEP(256u, w.y)
                PB_STEP(512u, w.z)
                PB_STEP(768u, w.w)
#undef PB_STEP
            }
            float r0, r1, r2, r3;
            asm volatile("mov.b64 {%0,%1},%2;" : "=f"(r0), "=f"(r1) : "l"(a01));
            asm volatile("mov.b64 {%0,%1},%2;" : "=f"(r2), "=f"(r3) : "l"(a23));
            if (nB < GEFFN) {
                int bb = bpg * 4;
                G2[(size_t)(bb + 0) * GEFFN + nB] = r0 + biasv;
                G2[(size_t)(bb + 1) * GEFFN + nB] = r1 + biasv;
                G2[(size_t)(bb + 2) * GEFFN + nB] = r2 + biasv;
                G2[(size_t)(bb + 3) * GEFFN + nB] = r3 + biasv;
            }
        }
        gbar(++bar, tid, cta);   // G2 ready
    }

    // final GRU update: row 63
    if (cta < 64) {
        int row = 63;
        const float* Gp = G2 + (size_t)b * GEFFN;
        const float* xi = XI + ((size_t)b * NSEQ + row) * G3;
        const float* xp = XP + ((size_t)b * NSEQ + row) * G3;
        const float* q  = Hin + ((size_t)b * NSEQ + row) * HID;
        float* h1r = H1 + ((size_t)b * NSEQ + row) * HID;
        for (int d = tid; d < HID; d += 256) {
            float Md = __ldcg(Gp + 1800 + d);
            float r  = sigf(xi[d]       + __ldcg(Gp + d));
            float z  = sigf(xi[300 + d] + __ldcg(Gp + 300 + d));
            float nn = tanhf(xi[600 + d] + r * __ldcg(Gp + 600 + d));
            float Cc = (1.f - z) * nn + z * Md;
            float r2 = sigf(__ldcg(Gp + 900 + d)  + xp[d]);
            float z2 = sigf(__ldcg(Gp + 1200 + d) + xp[300 + d]);
            float n2 = tanhf(__ldcg(Gp + 1500 + d) + r2 * xp[600 + d]);
            float Pp = (1.f - z2) * n2 + z2 * q[d];
            h1r[d] = Cc + Pp;
        }
    }
}

__global__ void k_concat(const float* __restrict__ feat) {
    int r = blockIdx.x;
    for (int c = threadIdx.x; c < KCAT; c += blockDim.x) {
        float v;
        if (c < 1500) {
            int seg = c / 300, off = c - seg * 300;
            v = g_H[seg * HSZ + r * HID + off];
        } else {
            v = feat[r * EMB + (c - 1500)];
        }
        g_Hcat[r * KCAT + c] = v;
    }
}

extern "C" void kernel_launch(void* const* d_in, const int* in_sizes, int n_in,
                              void* d_out, int out_size) {
    const float* features = (const float*)d_in[0];
    const int*   speakers = (const int*)d_in[1];
    const float* w_in   = (const float*)d_in[2];
    const float* b_in   = (const float*)d_in[3];
    const float* gat_wq = (const float*)d_in[4];
    const float* gat_wk = (const float*)d_in[5];
    const float* gat_b  = (const float*)d_in[6];
    const float* wr0    = (const float*)d_in[7];
    const float* wr1    = (const float*)d_in[8];
    const float* wih_c  = (const float*)d_in[9];
    const float* whh_c  = (const float*)d_in[10];
    const float* bih_c  = (const float*)d_in[11];
    const float* bhh_c  = (const float*)d_in[12];
    const float* wih_p  = (const float*)d_in[13];
    const float* whh_p  = (const float*)d_in[14];
    const float* bih_p  = (const float*)d_in[15];
    const float* bhh_p  = (const float*)d_in[16];
    const float* w1 = (const float*)d_in[17];
    const float* b1 = (const float*)d_in[18];
    const float* w2 = (const float*)d_in[19];
    const float* b2 = (const float*)d_in[20];
    const float* w3 = (const float*)d_in[21];
    const float* b3 = (const float*)d_in[22];

    float *H, *XIp, *XPp, *Wr2Tp, *WGp, *Geffp, *uTp, *G2p, *Hcatp, *h1p, *h2p;
    int *startp;
    cudaGetSymbolAddress((void**)&H,     g_H);
    cudaGetSymbolAddress((void**)&XIp,   g_XI);
    cudaGetSymbolAddress((void**)&XPp,   g_XP);
    cudaGetSymbolAddress((void**)&Wr2Tp, g_Wr2T);
    cudaGetSymbolAddress((void**)&WGp,   g_WG);
    cudaGetSymbolAddress((void**)&Geffp, g_Geff);
    cudaGetSymbolAddress((void**)&uTp,   g_uT);
    cudaGetSymbolAddress((void**)&G2p,   g_G2);
    cudaGetSymbolAddress((void**)&startp,g_start);
    cudaGetSymbolAddress((void**)&Hcatp, g_Hcat);
    cudaGetSymbolAddress((void**)&h1p,   g_h1);
    cudaGetSymbolAddress((void**)&h2p,   g_h2);

    cudaFuncSetAttribute(persist_layer,
                         cudaFuncAttributeMaxDynamicSharedMemorySize,
                         DSMEM_FLOATS * 4);

    const int MROWS = BATCH * NSEQ;

    k_start<<<BATCH, NSEQ>>>(speakers, startp);

    gemm128<<<dim3((HID + 63) / 64, MROWS / 128), 256>>>(
        features, w_in, b_in, H, MROWS, HID, EMB, 1);

    for (int l = 0; l < 4; l++) {
        const float* Hin = H + l * HSZ;
        float* H1 = H + (l + 1) * HSZ;
        const float* wih_c_l = wih_c + l * G3 * HID;
        const float* whh_c_l = whh_c + l * G3 * HID;
        const float* wih_p_l = wih_p + l * G3 * HID;
        const float* whh_p_l = whh_p + l * G3 * HID;
        const float* bhh_c_l = bhh_c + l * G3;
        const float* bih_c_l = bih_c + l * G3;
        const float* bih_p_l = bih_p + l * G3;
        const float* bhh_p_l = bhh_p + l * G3;
        const float* wq_l = gat_wq + l * HID;
        const float* wk_l = gat_wk + l * HID;

        gemm128<<<dim3((G3 + 63) / 64, MROWS / 128), 256>>>(
            Hin, wih_c_l, bih_c_l, XIp, MROWS, G3, HID, 0);
        gemm128<<<dim3((G3 + 63) / 64, MROWS / 128), 256>>>(
            Hin, whh_p_l, bhh_p_l, XPp, MROWS, G3, HID, 0);

        k_wr2<<<(300 * 600 + 255) / 256, 256>>>(wr0 + l * HID * HID, wr1 + l * HID * HID);
        k_wg<<<(1800 * 300 + 255) / 256, 256>>>(whh_c_l, wih_p_l);
        gemm128<<<dim3((600 + 63) / 64, (1800 + 127) / 128), 256>>>(
            WGp, Wr2Tp, (const float*)nullptr, Geffp, 1800, 600, 300, 0);

        k_reset<<<1, 1>>>();
        persist_layer<<<NCTA, 256, DSMEM_FLOATS * 4>>>(
            Hin, H1, XIp, XPp, wq_l, wk_l, gat_b, l,
            speakers, startp, bhh_c_l, bih_p_l, Geffp, uTp, G2p);
    }

    k_concat<<<MROWS, 256>>>(features);

    gemm128<<<dim3((HID + 63) / 64, MROWS / 128), 256>>>(
        Hcatp, w1, b1, h1p, MROWS, HID, KCAT, 1);
    gemm128<<<dim3((HID + 63) / 64, MROWS / 128), 256>>>(
        h1p, w2, b2, h2p, MROWS, HID, HID, 1);
    gemm128<<<dim3(1, MROWS / 128), 256>>>(
        h2p, w3, b3, (float*)d_out, MROWS, 7, HID, 0);
}

// round 9
// speedup vs baseline: 1.6301x; 1.0780x over previous
#include <cuda_runtime.h>
#include <math.h>

#define HID   300
#define G3    900
#define NSEQ  64
#define BATCH 64
#define EMB   1024
#define KCAT  2524
#define HSZ   (BATCH*NSEQ*HID)
#define NCTA  132
#define GEFFN 2100
#define DSMEM_FLOATS (16*604 + 600*64)

__device__ float g_H[5 * HSZ];
__device__ float g_XIP[BATCH * NSEQ * 1800];   // [XI | XP] per row
__device__ float g_WX[1800 * HID];             // [wih_c ; whh_p]
__device__ float g_bX[1800];                   // [bih_c ; bhh_p]
__device__ float g_Wr2T[600 * HID];
__device__ float g_WG[1800 * HID];             // [whh_c ; wih_p]
__device__ float g_Geff[GEFFN * 600];
__device__ float g_uT[600 * BATCH];            // transposed: uT[d*64 + b]
__device__ float g_G2[BATCH * GEFFN];
__device__ int   g_start[BATCH * NSEQ];
__device__ float g_Hcat[BATCH * NSEQ * KCAT];
__device__ float g_h1[BATCH * NSEQ * HID];
__device__ float g_h2[BATCH * NSEQ * HID];

__device__ volatile unsigned g_cnt;
__device__ volatile unsigned g_gen;

__device__ __forceinline__ float sigf(float x) {
    return __fdividef(1.f, 1.f + __expf(-x));
}
__device__ __forceinline__ float tanhfast(float x) {
    return __fdividef(2.f, 1.f + __expf(-2.f * x)) - 1.f;
}

// 256-thread reductions: shuffle + 8-slot smem
__device__ __forceinline__ float bsum(float v, float* s8) {
    int tid = threadIdx.x;
#pragma unroll
    for (int o = 16; o > 0; o >>= 1) v += __shfl_xor_sync(0xffffffffu, v, o);
    if ((tid & 31) == 0) s8[tid >> 5] = v;
    __syncthreads();
    if (tid < 32) {
        float t = (tid < 8) ? s8[tid] : 0.f;
#pragma unroll
        for (int o = 4; o > 0; o >>= 1) t += __shfl_xor_sync(0xffffffffu, t, o);
        if (tid == 0) s8[0] = t;
    }
    __syncthreads();
    float r = s8[0];
    __syncthreads();
    return r;
}
__device__ __forceinline__ float bmax(float v, float* s8) {
    int tid = threadIdx.x;
#pragma unroll
    for (int o = 16; o > 0; o >>= 1) v = fmaxf(v, __shfl_xor_sync(0xffffffffu, v, o));
    if ((tid & 31) == 0) s8[tid >> 5] = v;
    __syncthreads();
    if (tid < 32) {
        float t = (tid < 8) ? s8[tid] : -1e30f;
#pragma unroll
        for (int o = 4; o > 0; o >>= 1) t = fmaxf(t, __shfl_xor_sync(0xffffffffu, t, o));
        if (tid == 0) s8[0] = t;
    }
    __syncthreads();
    float r = s8[0];
    __syncthreads();
    return r;
}

__device__ __forceinline__ void gbar(unsigned bar, int tid, int cta) {
    __syncthreads();
    if (tid == 0) {
        __threadfence();
        asm volatile("red.global.add.u32 [%0], %1;" :: "l"((const void*)&g_cnt), "r"(1u) : "memory");
        if (cta == 0) {
            while (g_cnt < NCTA * bar) __nanosleep(20);
            __threadfence();
            g_gen = bar;
        } else {
            while (g_gen < bar) __nanosleep(20);
        }
        asm volatile("fence.acq_rel.gpu;" ::: "memory");
    }
    __syncthreads();
}

__global__ void k_start(const int* __restrict__ spk, int* __restrict__ start) {
    int b = blockIdx.x, i = threadIdx.x;
    int s = spk[b * NSEQ + i];
    int last = -1;
    for (int j = 0; j < i; j++)
        if (spk[b * NSEQ + j] == s) last = j;
    start[b * NSEQ + i] = last > 0 ? last : 0;
}

// ---- per-layer prep: WX/bX/WG/Wr2T/Geff-bottom + barrier reset ----
__global__ void k_prep(const float* __restrict__ wih_c, const float* __restrict__ whh_p,
                       const float* __restrict__ bih_c, const float* __restrict__ bhh_p,
                       const float* __restrict__ whh_c, const float* __restrict__ wih_p,
                       const float* __restrict__ wr0,   const float* __restrict__ wr1)
{
    int idx = blockIdx.x * blockDim.x + threadIdx.x;
    if (idx < 1800 * 300) {
        int n = idx / 300, d = idx - n * 300;
        g_WX[idx] = (n < 900) ? wih_c[n * 300 + d] : whh_p[(n - 900) * 300 + d];
        g_WG[idx] = (n < 900) ? whh_c[n * 300 + d] : wih_p[(n - 900) * 300 + d];
    }
    if (idx < 300 * 600) {
        int d = idx / 600, e = idx - d * 600;
        float v = (e < 300) ? wr0[d * 300 + e] : wr1[d * 300 + (e - 300)];
        g_Wr2T[e * 300 + d] = v;
        g_Geff[(1800 + d) * 600 + e] = v;
    }
    if (idx < 1800) g_bX[idx] = (idx < 900) ? bih_c[idx] : bhh_p[idx - 900];
    if (idx == 0) { g_cnt = 0; g_gen = 0; }
}

// ---- dense GEMM: C=A@B^T+bias (opt relu). BM=128,BN=128,BK=16, 8x8 micro ----
__global__ void __launch_bounds__(256, 2) gemm8x8(
    const float* __restrict__ A, const float* __restrict__ B,
    const float* __restrict__ bias, float* __restrict__ C,
    int M, int N, int K, int relu)
{
    __shared__ float sA[16 * 132];
    __shared__ float sB[16 * 132];
    int tid = threadIdx.x;
    int m0 = blockIdx.y * 128, n0 = blockIdx.x * 128;
    int tm = tid & 15, tn = tid >> 4;
    int lr = tid >> 2, lk = (tid & 3) * 4;
    float acc[8][8];
#pragma unroll
    for (int i = 0; i < 8; i++)
#pragma unroll
        for (int j = 0; j < 8; j++) acc[i][j] = 0.f;

    for (int k0 = 0; k0 < K; k0 += 16) {
#pragma unroll
        for (int h = 0; h < 2; h++) {
            int m = lr + h * 64, gm = m0 + m, kb = k0 + lk;
            float4 av = make_float4(0.f, 0.f, 0.f, 0.f);
            if (gm < M) {
                if (kb + 3 < K) av = *(const float4*)(A + (size_t)gm * K + kb);
                else {
                    if (kb     < K) av.x = A[(size_t)gm * K + kb];
                    if (kb + 1 < K) av.y = A[(size_t)gm * K + kb + 1];
                    if (kb + 2 < K) av.z = A[(size_t)gm * K + kb + 2];
                }
            }
            sA[(lk + 0) * 132 + m] = av.x;
            sA[(lk + 1) * 132 + m] = av.y;
            sA[(lk + 2) * 132 + m] = av.z;
            sA[(lk + 3) * 132 + m] = av.w;

            int gn = n0 + m;
            float4 bv = make_float4(0.f, 0.f, 0.f, 0.f);
            if (gn < N) {
                if (kb + 3 < K) bv = *(const float4*)(B + (size_t)gn * K + kb);
                else {
                    if (kb     < K) bv.x = B[(size_t)gn * K + kb];
                    if (kb + 1 < K) bv.y = B[(size_t)gn * K + kb + 1];
                    if (kb + 2 < K) bv.z = B[(size_t)gn * K + kb + 2];
                }
            }
            sB[(lk + 0) * 132 + m] = bv.x;
            sB[(lk + 1) * 132 + m] = bv.y;
            sB[(lk + 2) * 132 + m] = bv.z;
            sB[(lk + 3) * 132 + m] = bv.w;
        }
        __syncthreads();
#pragma unroll
        for (int kk = 0; kk < 16; kk++) {
            float4 xa0 = *(const float4*)(sA + kk * 132 + tm * 4);
            float4 xa1 = *(const float4*)(sA + kk * 132 + 64 + tm * 4);
            float4 xb0 = *(const float4*)(sB + kk * 132 + tn * 4);
            float4 xb1 = *(const float4*)(sB + kk * 132 + 64 + tn * 4);
            float a[8] = {xa0.x, xa0.y, xa0.z, xa0.w, xa1.x, xa1.y, xa1.z, xa1.w};
            float bv[8] = {xb0.x, xb0.y, xb0.z, xb0.w, xb1.x, xb1.y, xb1.z, xb1.w};
#pragma unroll
            for (int i = 0; i < 8; i++)
#pragma unroll
                for (int j = 0; j < 8; j++) acc[i][j] += a[i] * bv[j];
        }
        __syncthreads();
    }
#pragma unroll
    for (int i = 0; i < 8; i++) {
        int m = m0 + ((i < 4) ? (tm * 4 + i) : (64 + tm * 4 + i - 4));
        if (m >= M) continue;
#pragma unroll
        for (int j = 0; j < 8; j++) {
            int n = n0 + ((j < 4) ? (tn * 4 + j) : (64 + tn * 4 + j - 4));
            if (n >= N) continue;
            float v = acc[i][j] + (bias ? bias[n] : 0.f);
            if (relu) v = fmaxf(v, 0.f);
            C[(size_t)m * N + n] = v;
        }
    }
}

// ---------------- persistent per-layer scan kernel ----------------
__global__ void __launch_bounds__(256, 1) persist_layer(
    const float* __restrict__ Hin, float* __restrict__ H1,
    const float* __restrict__ XIP,
    const float* __restrict__ wq, const float* __restrict__ wk,
    const float* __restrict__ gatb, int layer,
    const int* __restrict__ spk, const int* __restrict__ start,
    const float* __restrict__ bhh_c, const float* __restrict__ bih_p,
    const float* __restrict__ Geff, float* __restrict__ uT,
    float* __restrict__ G2)
{
    extern __shared__ float dsm[];
    float* sW = dsm;                 // 16*604
    float* sU = dsm + 16 * 604;      // 600*64, layout [d*64 + b]

    __shared__ float s8[8];
    __shared__ float s_w0[64];
    __shared__ float s_w1[64];
    __shared__ float s_kdot[64];

    const int tid = threadIdx.x;
    const int cta = blockIdx.x;
    const int b = cta;
    const int n0 = cta * 16;

    for (int idx = tid; idx < 16 * 600; idx += 256) {
        int c = idx / 600, k = idx - c * 600;
        int n = n0 + c;
        sW[c * 604 + k] = (n < GEFFN) ? Geff[(size_t)n * 600 + k] : 0.f;
    }

    const int cB = tid & 15, bpg = tid >> 4;
    const int nB = n0 + cB;
    float biasv = 0.f;
    if (nB < 900) biasv = bhh_c[nB];
    else if (nB < 1800) biasv = bih_p[nB - 900];
    const float4* wrow = (const float4*)(sW + cB * 604);
    unsigned uAddr = (unsigned)__cvta_generic_to_shared(sU) + bpg * 16;

    unsigned bar = 0;
    const float gb = gatb[layer];

    if (cta < 64) {
        const float* xi = XIP + (size_t)b * NSEQ * 1800;
        const float* xp = xi + 900;
        const float* x0 = Hin + (size_t)b * NSEQ * HID;
        float* h1 = H1 + (size_t)b * NSEQ * HID;
        float kp = 0.f;
        for (int d = tid; d < HID; d += 256) {
            float r  = sigf(xi[d] + bhh_c[d]);
            float z  = sigf(xi[300 + d] + bhh_c[300 + d]);
            float nn = tanhfast(xi[600 + d] + r * bhh_c[600 + d]);
            float C0 = (1.f - z) * nn;
            float r2 = sigf(bih_p[d] + xp[d]);
            float z2 = sigf(bih_p[300 + d] + xp[300 + d]);
            float n2 = tanhfast(bih_p[600 + d] + r2 * xp[600 + d]);
            float P0 = (1.f - z2) * n2 + z2 * x0[d];
            float h = C0 + P0;
            h1[d] = h;
            kp += h * wk[d];
        }
        float ks = bsum(kp, s8);
        if (tid == 0) s_kdot[0] = ks;
    }
    __syncthreads();

    for (int i = 1; i <= 63; i++) {
        // ===== phase A (CTAs 0..63): GRU row i-1, attention -> uT =====
        if (cta < 64) {
            if (i >= 2) {
                int row = i - 1;
                const float* Gp = G2 + (size_t)b * GEFFN;
                const float* xi = XIP + ((size_t)b * NSEQ + row) * 1800;
                const float* xp = xi + 900;
                const float* q  = Hin + ((size_t)b * NSEQ + row) * HID;
                float* h1r = H1 + ((size_t)b * NSEQ + row) * HID;
                float kp = 0.f;
                for (int d = tid; d < HID; d += 256) {
                    float Md = __ldcg(Gp + 1800 + d);
                    float r  = sigf(xi[d]       + __ldcg(Gp + d));
                    float z  = sigf(xi[300 + d] + __ldcg(Gp + 300 + d));
                    float nn = tanhfast(xi[600 + d] + r * __ldcg(Gp + 600 + d));
                    float Cc = (1.f - z) * nn + z * Md;
                    float r2 = sigf(__ldcg(Gp + 900 + d)  + xp[d]);
                    float z2 = sigf(__ldcg(Gp + 1200 + d) + xp[300 + d]);
                    float n2 = tanhfast(__ldcg(Gp + 1500 + d) + r2 * xp[600 + d]);
                    float Pp = (1.f - z2) * n2 + z2 * q[d];
                    float h = Cc + Pp;
                    h1r[d] = h;
                    kp += h * wk[d];
                }
                float ks = bsum(kp, s8);
                if (tid == 0) s_kdot[row] = ks;
                __syncthreads();
            }
            const float* qrow = Hin + ((size_t)b * NSEQ + i) * HID;
            float qp = 0.f;
            for (int d = tid; d < HID; d += 256) qp += qrow[d] * wq[d];
            float qd = bsum(qp, s8);

            int st = start[b * NSEQ + i];
            int cnt = i - st;
            int spki = spk[b * NSEQ + i];

            float aj = -1e30f;
            if (tid < cnt) aj = qd + s_kdot[st + tid] + gb;
            float mx = bmax(aj, s8);
            float e = (tid < cnt) ? __expf(aj - mx) : 0.f;
            float se = bsum(e, s8);
            if (tid < cnt) {
                float w = __fdividef(e, se);
                float smv = (spk[b * NSEQ + st + tid] == spki) ? 1.f : 0.f;
                s_w0[tid] = w * smv;
                s_w1[tid] = w * (1.f - smv);
            }
            __syncthreads();
            for (int d = tid; d < 600; d += 256) {
                int ei = (d < 300) ? d : d - 300;
                const float* wt = (d < 300) ? s_w0 : s_w1;
                const float* base = H1 + ((size_t)b * NSEQ + st) * HID + ei;
                float acc = 0.f;
#pragma unroll 4
                for (int j = 0; j < cnt; j++)
                    acc += wt[j] * base[j * HID];
                __stcg(uT + d * 64 + b, acc);
            }
        }
        gbar(++bar, tid, cta);   // u ready

        // ===== stage uT into SMEM (all CTAs) =====
        {
            const float4* src = (const float4*)uT;
            float4* dst = (float4*)sU;
            for (int idx = tid; idx < 9600; idx += 256)
                dst[idx] = __ldcg(src + idx);
        }
        __syncthreads();

        // ===== phase B: G2 = u @ Geff^T + bias (f32x2 packed) =====
        {
            unsigned long long a01 = 0ull, a23 = 0ull;
            for (int k4 = 0; k4 < 150; k4++) {
                float4 w = wrow[k4];
                unsigned base = uAddr + (unsigned)(k4 * 1024);
#define PB_STEP(OFF, WC) { \
                unsigned long long p01, p23, wp; \
                asm volatile("ld.shared.v2.u64 {%0,%1},[%2];" : "=l"(p01), "=l"(p23) : "r"(base + OFF)); \
                asm volatile("mov.b64 %0,{%1,%1};" : "=l"(wp) : "f"(WC)); \
                asm volatile("fma.rn.f32x2 %0,%1,%2,%0;" : "+l"(a01) : "l"(p01), "l"(wp)); \
                asm volatile("fma.rn.f32x2 %0,%1,%2,%0;" : "+l"(a23) : "l"(p23), "l"(wp)); }
                PB_STEP(0u,   w.x)
                PB_STEP(256u, w.y)
                PB_STEP(512u, w.z)
                PB_STEP(768u, w.w)
#undef PB_STEP
            }
            float r0, r1, r2, r3;
            asm volatile("mov.b64 {%0,%1},%2;" : "=f"(r0), "=f"(r1) : "l"(a01));
            asm volatile("mov.b64 {%0,%1},%2;" : "=f"(r2), "=f"(r3) : "l"(a23));
            if (nB < GEFFN) {
                int bb = bpg * 4;
                G2[(size_t)(bb + 0) * GEFFN + nB] = r0 + biasv;
                G2[(size_t)(bb + 1) * GEFFN + nB] = r1 + biasv;
                G2[(size_t)(bb + 2) * GEFFN + nB] = r2 + biasv;
                G2[(size_t)(bb + 3) * GEFFN + nB] = r3 + biasv;
            }
        }
        gbar(++bar, tid, cta);   // G2 ready
    }

    // final GRU update: row 63
    if (cta < 64) {
        int row = 63;
        const float* Gp = G2 + (size_t)b * GEFFN;
        const float* xi = XIP + ((size_t)b * NSEQ + row) * 1800;
        const float* xp = xi + 900;
        const float* q  = Hin + ((size_t)b * NSEQ + row) * HID;
        float* h1r = H1 + ((size_t)b * NSEQ + row) * HID;
        for (int d = tid; d < HID; d += 256) {
            float Md = __ldcg(Gp + 1800 + d);
            float r  = sigf(xi[d]       + __ldcg(Gp + d));
            float z  = sigf(xi[300 + d] + __ldcg(Gp + 300 + d));
            float nn = tanhfast(xi[600 + d] + r * __ldcg(Gp + 600 + d));
            float Cc = (1.f - z) * nn + z * Md;
            float r2 = sigf(__ldcg(Gp + 900 + d)  + xp[d]);
            float z2 = sigf(__ldcg(Gp + 1200 + d) + xp[300 + d]);
            float n2 = tanhfast(__ldcg(Gp + 1500 + d) + r2 * xp[600 + d]);
            float Pp = (1.f - z2) * n2 + z2 * q[d];
            h1r[d] = Cc + Pp;
        }
    }
}

__global__ void k_concat(const float* __restrict__ feat) {
    int r = blockIdx.x;
    for (int c = threadIdx.x; c < KCAT; c += blockDim.x) {
        float v;
        if (c < 1500) {
            int seg = c / 300, off = c - seg * 300;
            v = g_H[seg * HSZ + r * HID + off];
        } else {
            v = feat[r * EMB + (c - 1500)];
        }
        g_Hcat[r * KCAT + c] = v;
    }
}

extern "C" void kernel_launch(void* const* d_in, const int* in_sizes, int n_in,
                              void* d_out, int out_size) {
    const float* features = (const float*)d_in[0];
    const int*   speakers = (const int*)d_in[1];
    const float* w_in   = (const float*)d_in[2];
    const float* b_in   = (const float*)d_in[3];
    const float* gat_wq = (const float*)d_in[4];
    const float* gat_wk = (const float*)d_in[5];
    const float* gat_b  = (const float*)d_in[6];
    const float* wr0    = (const float*)d_in[7];
    const float* wr1    = (const float*)d_in[8];
    const float* wih_c  = (const float*)d_in[9];
    const float* whh_c  = (const float*)d_in[10];
    const float* bih_c  = (const float*)d_in[11];
    const float* bhh_c  = (const float*)d_in[12];
    const float* wih_p  = (const float*)d_in[13];
    const float* whh_p  = (const float*)d_in[14];
    const float* bih_p  = (const float*)d_in[15];
    const float* bhh_p  = (const float*)d_in[16];
    const float* w1 = (const float*)d_in[17];
    const float* b1 = (const float*)d_in[18];
    const float* w2 = (const float*)d_in[19];
    const float* b2 = (const float*)d_in[20];
    const float* w3 = (const float*)d_in[21];
    const float* b3 = (const float*)d_in[22];

    float *H, *XIPp, *WXp, *bXp, *Wr2Tp, *WGp, *Geffp, *uTp, *G2p, *Hcatp, *h1p, *h2p;
    int *startp;
    cudaGetSymbolAddress((void**)&H,     g_H);
    cudaGetSymbolAddress((void**)&XIPp,  g_XIP);
    cudaGetSymbolAddress((void**)&WXp,   g_WX);
    cudaGetSymbolAddress((void**)&bXp,   g_bX);
    cudaGetSymbolAddress((void**)&Wr2Tp, g_Wr2T);
    cudaGetSymbolAddress((void**)&WGp,   g_WG);
    cudaGetSymbolAddress((void**)&Geffp, g_Geff);
    cudaGetSymbolAddress((void**)&uTp,   g_uT);
    cudaGetSymbolAddress((void**)&G2p,   g_G2);
    cudaGetSymbolAddress((void**)&startp,g_start);
    cudaGetSymbolAddress((void**)&Hcatp, g_Hcat);
    cudaGetSymbolAddress((void**)&h1p,   g_h1);
    cudaGetSymbolAddress((void**)&h2p,   g_h2);

    cudaFuncSetAttribute(persist_layer,
                         cudaFuncAttributeMaxDynamicSharedMemorySize,
                         DSMEM_FLOATS * 4);

    const int MROWS = BATCH * NSEQ;

    // launch order puts persist_layer at #6 so ncu (-s 5 -c 1) profiles it
    k_start<<<BATCH, NSEQ>>>(speakers, startp);                                   // 1

    gemm8x8<<<dim3((HID + 127) / 128, MROWS / 128), 256>>>(
        features, w_in, b_in, H, MROWS, HID, EMB, 1);                             // 2

    for (int l = 0; l < 4; l++) {
        const float* Hin = H + l * HSZ;
        float* H1 = H + (l + 1) * HSZ;
        const float* wq_l = gat_wq + l * HID;
        const float* wk_l = gat_wk + l * HID;

        k_prep<<<(1800 * 300 + 255) / 256, 256>>>(                                 // 3
            wih_c + l * G3 * HID, whh_p + l * G3 * HID,
            bih_c + l * G3, bhh_p + l * G3,
            whh_c + l * G3 * HID, wih_p + l * G3 * HID,
            wr0 + l * HID * HID, wr1 + l * HID * HID);

        gemm8x8<<<dim3((600 + 127) / 128, (1800 + 127) / 128), 256>>>(             // 4
            WGp, Wr2Tp, (const float*)nullptr, Geffp, 1800, 600, 300, 0);

        gemm8x8<<<dim3((1800 + 127) / 128, MROWS / 128), 256>>>(                   // 5
            Hin, WXp, bXp, XIPp, MROWS, 1800, HID, 0);

        persist_layer<<<NCTA, 256, DSMEM_FLOATS * 4>>>(                            // 6
            Hin, H1, XIPp, wq_l, wk_l, gat_b, l,
            speakers, startp, bhh_c + l * G3, bih_p + l * G3, Geffp, uTp, G2p);
    }

    k_concat<<<MROWS, 256>>>(features);

    gemm8x8<<<dim3((HID + 127) / 128, MROWS / 128), 256>>>(
        Hcatp, w1, b1, h1p, MROWS, HID, KCAT, 1);
    gemm8x8<<<dim3((HID + 127) / 128, MROWS / 128), 256>>>(
        h1p, w2, b2, h2p, MROWS, HID, HID, 1);
    gemm8x8<<<dim3(1, MROWS / 128), 256>>>(
        h2p, w3, b3, (float*)d_out, MROWS, 7, HID, 0);
}